// round 8
// baseline (speedup 1.0000x reference)
#include <cuda_runtime.h>
#include <cstdint>

// Problem constants
#define D_MODEL 1024
#define S_LEN   2048
#define NH      16
#define HDIM    64
#define NBATCH  2
#define NTOK    (NBATCH * S_LEN)   // 4096

// Scratch (static __device__ globals — allocation-free per harness rules)
__device__ float g_Q [NTOK * D_MODEL];
__device__ float g_K [NTOK * D_MODEL];
__device__ float g_V [NTOK * D_MODEL];
__device__ float g_AO[NTOK * D_MODEL];

// ---------------------------------------------------------------------------
// Helpers (legacy tensor-core path only — tcgen05 is unavailable: the harness
// emits .target sm_100 PTX, which rejects all tcgen05 instructions).
// ---------------------------------------------------------------------------
__device__ __forceinline__ uint32_t f2tf32(float x) {
    uint32_t y; asm("cvt.rna.tf32.f32 %0, %1;" : "=r"(y) : "f"(x)); return y;
}
// D[16x8] += A[16x8] * B[8x8], tf32 inputs (HW-verified in R5/R6).
__device__ __forceinline__ void mma_tf32(float* d, const uint32_t* a, const uint32_t* b) {
    asm volatile(
        "mma.sync.aligned.m16n8k8.row.col.f32.tf32.tf32.f32 "
        "{%0,%1,%2,%3}, {%4,%5,%6,%7}, {%8,%9}, {%0,%1,%2,%3};"
        : "+f"(d[0]), "+f"(d[1]), "+f"(d[2]), "+f"(d[3])
        : "r"(a[0]), "r"(a[1]), "r"(a[2]), "r"(a[3]), "r"(b[0]), "r"(b[1]));
}

// ===========================================================================
// Tensor-core tf32 GEMM, retiled for occupancy 2.
// C[m][n] = sum_k A[m][k]*B[n][k] + bias[n].
// 128(M) x 64(N) CTA tile, k-stage 32, double-buffered smem, 256 threads,
// 8 warps in 4x2 -> warp tile 32x32 -> acc = 32 regs/thread (~90 total).
// Rows padded to 36 words: fragment LDS bank-conflict-free.
// ===========================================================================
#define ROWF 36
#define STG_WORDS_AB (192 * ROWF)                 // A(128 rows) + B(64 rows)
#define GEMM_SMEM_BYTES (2 * STG_WORDS_AB * 4)    // double buffer = 55296 B

__device__ __forceinline__ void gemm_tile_body(
    const float* __restrict__ A, const float* __restrict__ B,
    const float* __restrict__ bias, float* __restrict__ C,
    int bM, int bN, uint32_t* sm)
{
    const int tid  = threadIdx.x;
    const int lane = tid & 31;
    const int wid  = tid >> 5;
    const int g    = lane >> 2;
    const int t    = lane & 3;
    const int wm   = (wid >> 1) * 32;   // warp m-base (0/32/64/96)
    const int wn   = (wid & 1) * 32;    // warp n-base (0/32)

    // Staging: A = 128x32 (4 float4/thread), B = 64x32 (2 float4/thread).
    const int c4 = tid & 7;             // float4 column within 32-word row
    const int rA = tid >> 3;            // base row 0..31 (rows rA + i*32)
    const float* gA = A + (size_t)(bM + rA) * D_MODEL + c4 * 4;
    const float* gB = B + (size_t)(bN + rA) * D_MODEL + c4 * 4;
    const int so = rA * ROWF + c4 * 4;

    float acc[8][4];
    #pragma unroll
    for (int i = 0; i < 8; i++)
        #pragma unroll
        for (int j = 0; j < 4; j++) acc[i][j] = 0.0f;

    // Prologue: stage 0 into buffer 0.
    {
        uint32_t* dA = sm;
        uint32_t* dB = sm + 128 * ROWF;
        #pragma unroll
        for (int i = 0; i < 4; i++) {
            float4 v = *(const float4*)(gA + (size_t)i * 32 * D_MODEL);
            uint4 w = {f2tf32(v.x), f2tf32(v.y), f2tf32(v.z), f2tf32(v.w)};
            *(uint4*)(dA + so + i * 32 * ROWF) = w;
        }
        #pragma unroll
        for (int i = 0; i < 2; i++) {
            float4 v = *(const float4*)(gB + (size_t)i * 32 * D_MODEL);
            uint4 w = {f2tf32(v.x), f2tf32(v.y), f2tf32(v.z), f2tf32(v.w)};
            *(uint4*)(dB + so + i * 32 * ROWF) = w;
        }
    }
    __syncthreads();

    for (int s = 0; s < 32; s++) {
        const uint32_t* bufA = sm + (s & 1) * STG_WORDS_AB;
        const uint32_t* bufB = bufA + 128 * ROWF;

        // Register prefetch of next stage (hidden under MMA work).
        float4 ra[4], rb[2];
        if (s + 1 < 32) {
            const int kt = (s + 1) * 32;
            #pragma unroll
            for (int i = 0; i < 4; i++)
                ra[i] = *(const float4*)(gA + (size_t)i * 32 * D_MODEL + kt);
            #pragma unroll
            for (int i = 0; i < 2; i++)
                rb[i] = *(const float4*)(gB + (size_t)i * 32 * D_MODEL + kt);
        }

        // Compute: 4 k8-steps, 8 mma each (2 m-tiles x 4 n-tiles).
        const uint32_t* pA = bufA + (wm + g) * ROWF + t;
        const uint32_t* pB = bufB + (wn + g) * ROWF + t;
        #pragma unroll
        for (int ks = 0; ks < 4; ks++) {
            const int k0 = ks * 8;
            uint32_t af[2][4], bf[4][2];
            #pragma unroll
            for (int i = 0; i < 2; i++) {
                af[i][0] = pA[(i * 16 + 0) * ROWF + k0];
                af[i][1] = pA[(i * 16 + 8) * ROWF + k0];
                af[i][2] = pA[(i * 16 + 0) * ROWF + k0 + 4];
                af[i][3] = pA[(i * 16 + 8) * ROWF + k0 + 4];
            }
            #pragma unroll
            for (int j = 0; j < 4; j++) {
                bf[j][0] = pB[j * 8 * ROWF + k0];
                bf[j][1] = pB[j * 8 * ROWF + k0 + 4];
            }
            #pragma unroll
            for (int i = 0; i < 2; i++)
                #pragma unroll
                for (int j = 0; j < 4; j++)
                    mma_tf32(acc[i * 4 + j], af[i], bf[j]);
        }

        // Store prefetched stage into the other buffer.
        if (s + 1 < 32) {
            uint32_t* dA = sm + ((s + 1) & 1) * STG_WORDS_AB;
            uint32_t* dB = dA + 128 * ROWF;
            #pragma unroll
            for (int i = 0; i < 4; i++) {
                uint4 w = {f2tf32(ra[i].x), f2tf32(ra[i].y), f2tf32(ra[i].z), f2tf32(ra[i].w)};
                *(uint4*)(dA + so + i * 32 * ROWF) = w;
            }
            #pragma unroll
            for (int i = 0; i < 2; i++) {
                uint4 w = {f2tf32(rb[i].x), f2tf32(rb[i].y), f2tf32(rb[i].z), f2tf32(rb[i].w)};
                *(uint4*)(dB + so + i * 32 * ROWF) = w;
            }
        }
        __syncthreads();
    }

    // Epilogue: bias + float2 stores.
    #pragma unroll
    for (int i = 0; i < 2; i++) {
        const int m0 = bM + wm + i * 16 + g;
        #pragma unroll
        for (int j = 0; j < 4; j++) {
            const int col = bN + wn + j * 8 + 2 * t;
            float2 bb = *(const float2*)(bias + col);
            float2 v0 = {acc[i * 4 + j][0] + bb.x, acc[i * 4 + j][1] + bb.y};
            float2 v1 = {acc[i * 4 + j][2] + bb.x, acc[i * 4 + j][3] + bb.y};
            *(float2*)(C + (size_t)m0 * D_MODEL + col)       = v0;
            *(float2*)(C + (size_t)(m0 + 8) * D_MODEL + col) = v1;
        }
    }
}

// Fused QKV: gridDim.z selects projection -> one launch, 1536 CTAs.
__global__ __launch_bounds__(256, 2)
void gemm_qkv(const float* __restrict__ X,
              const float* __restrict__ Wq, const float* __restrict__ bq,
              const float* __restrict__ Wk, const float* __restrict__ bk,
              const float* __restrict__ Wv, const float* __restrict__ bv)
{
    extern __shared__ uint32_t sm[];
    const float* B;  const float* bias;  float* C;
    if (blockIdx.z == 0)      { B = Wq; bias = bq; C = g_Q; }
    else if (blockIdx.z == 1) { B = Wk; bias = bk; C = g_K; }
    else                      { B = Wv; bias = bv; C = g_V; }
    gemm_tile_body(X, B, bias, C, blockIdx.y * 128, blockIdx.x * 64, sm);
}

__global__ __launch_bounds__(256, 2)
void gemm_out(const float* __restrict__ Wo, const float* __restrict__ bo,
              float* __restrict__ out)
{
    extern __shared__ uint32_t sm[];
    gemm_tile_body(g_AO, Wo, bo, out, blockIdx.y * 128, blockIdx.x * 64, sm);
}

// ===========================================================================
// Tensor-core causal flash attention (unchanged from R6 — verified).
// ===========================================================================
#define QT 128
#define KT 64
#define PAD 68
#define ATTN_SMEM_BYTES ((QT + KT + HDIM + QT) * PAD * 4)   // 104448 B

__global__ __launch_bounds__(256, 2)
void attn_mma()
{
    extern __shared__ uint32_t sma[];
    uint32_t* Qs = sma;                 // [128][68]  Q (pre-scaled, tf32)
    uint32_t* Ks = Qs + QT * PAD;       // [64][68]   K natural
    uint32_t* Vt = Ks + KT * PAD;       // [64][68]   V transposed [d][key]
    uint32_t* Ps = Vt + HDIM * PAD;     // [128][68]  P (tf32)

    const int tid  = threadIdx.x;
    const int lane = tid & 31;
    const int wid  = tid >> 5;
    const int g    = lane >> 2;
    const int t    = lane & 3;
    const int qt   = (int)(gridDim.x - 1) - (int)blockIdx.x;  // heavy tiles first
    const int h    = blockIdx.y;
    const int n    = blockIdx.z;
    const int qb0  = qt * QT;
    const int row0 = wid * 16;

    const size_t headbase = ((size_t)n * S_LEN) * D_MODEL + h * HDIM;

    {
        const float* Qg = g_Q + headbase + (size_t)qb0 * D_MODEL;
        #pragma unroll
        for (int i = 0; i < 8; i++) {
            int idx = tid + i * 256;
            int r = idx >> 4, c4 = idx & 15;
            float4 v = *(const float4*)(Qg + (size_t)r * D_MODEL + c4 * 4);
            uint4 w = {f2tf32(v.x * 0.125f), f2tf32(v.y * 0.125f),
                       f2tf32(v.z * 0.125f), f2tf32(v.w * 0.125f)};
            *(uint4*)(Qs + r * PAD + c4 * 4) = w;
        }
    }

    float m_i[2] = {-1e30f, -1e30f};
    float l_i[2] = {0.0f, 0.0f};
    float acc[8][4];
    #pragma unroll
    for (int i = 0; i < 8; i++)
        #pragma unroll
        for (int j = 0; j < 4; j++) acc[i][j] = 0.0f;

    const int nkb = (qb0 + QT) / KT;

    for (int kb = 0; kb < nkb; kb++) {
        __syncthreads();
        {
            const float* Kg = g_K + headbase + (size_t)kb * KT * D_MODEL;
            const float* Vg = g_V + headbase + (size_t)kb * KT * D_MODEL;
            #pragma unroll
            for (int i = 0; i < 4; i++) {
                int idx = tid + i * 256;
                int r = idx >> 4, c4 = idx & 15;
                float4 kv = *(const float4*)(Kg + (size_t)r * D_MODEL + c4 * 4);
                uint4 kw = {f2tf32(kv.x), f2tf32(kv.y), f2tf32(kv.z), f2tf32(kv.w)};
                *(uint4*)(Ks + r * PAD + c4 * 4) = kw;
                int rv = idx & 63, cv = idx >> 6;
                float4 vv = *(const float4*)(Vg + (size_t)rv * D_MODEL + cv * 4);
                Vt[(cv * 4 + 0) * PAD + rv] = f2tf32(vv.x);
                Vt[(cv * 4 + 1) * PAD + rv] = f2tf32(vv.y);
                Vt[(cv * 4 + 2) * PAD + rv] = f2tf32(vv.z);
                Vt[(cv * 4 + 3) * PAD + rv] = f2tf32(vv.w);
            }
        }
        __syncthreads();

        float s[8][4];
        #pragma unroll
        for (int i = 0; i < 8; i++)
            #pragma unroll
            for (int j = 0; j < 4; j++) s[i][j] = 0.0f;

        #pragma unroll
        for (int ks = 0; ks < 8; ks++) {
            const uint32_t* pa = Qs + (row0 + g) * PAD + ks * 8 + t;
            uint32_t a[4] = {pa[0], pa[8 * PAD], pa[4], pa[8 * PAD + 4]};
            #pragma unroll
            for (int nt = 0; nt < 8; nt++) {
                const uint32_t* pb = Ks + (nt * 8 + g) * PAD + ks * 8 + t;
                uint32_t b[2] = {pb[0], pb[4]};
                mma_tf32(s[nt], a, b);
            }
        }

        const int r0g = qb0 + row0 + g;
        if ((kb + 1) * KT - 1 > qb0 + row0) {
            #pragma unroll
            for (int nt = 0; nt < 8; nt++) {
                int c = kb * KT + nt * 8 + 2 * t;
                if (c     > r0g)     s[nt][0] = -1e30f;
                if (c + 1 > r0g)     s[nt][1] = -1e30f;
                if (c     > r0g + 8) s[nt][2] = -1e30f;
                if (c + 1 > r0g + 8) s[nt][3] = -1e30f;
            }
        }

        float mx0 = -1e30f, mx1 = -1e30f;
        #pragma unroll
        for (int nt = 0; nt < 8; nt++) {
            mx0 = fmaxf(mx0, fmaxf(s[nt][0], s[nt][1]));
            mx1 = fmaxf(mx1, fmaxf(s[nt][2], s[nt][3]));
        }
        mx0 = fmaxf(mx0, __shfl_xor_sync(0xFFFFFFFFu, mx0, 1));
        mx0 = fmaxf(mx0, __shfl_xor_sync(0xFFFFFFFFu, mx0, 2));
        mx1 = fmaxf(mx1, __shfl_xor_sync(0xFFFFFFFFu, mx1, 1));
        mx1 = fmaxf(mx1, __shfl_xor_sync(0xFFFFFFFFu, mx1, 2));

        const float mn0 = fmaxf(m_i[0], mx0);
        const float mn1 = fmaxf(m_i[1], mx1);
        const float co0 = __expf(m_i[0] - mn0);
        const float co1 = __expf(m_i[1] - mn1);
        m_i[0] = mn0; m_i[1] = mn1;

        float rs0 = 0.0f, rs1 = 0.0f;
        #pragma unroll
        for (int nt = 0; nt < 8; nt++) {
            s[nt][0] = __expf(s[nt][0] - mn0);
            s[nt][1] = __expf(s[nt][1] - mn0);
            s[nt][2] = __expf(s[nt][2] - mn1);
            s[nt][3] = __expf(s[nt][3] - mn1);
            rs0 += s[nt][0] + s[nt][1];
            rs1 += s[nt][2] + s[nt][3];
        }
        rs0 += __shfl_xor_sync(0xFFFFFFFFu, rs0, 1);
        rs0 += __shfl_xor_sync(0xFFFFFFFFu, rs0, 2);
        rs1 += __shfl_xor_sync(0xFFFFFFFFu, rs1, 1);
        rs1 += __shfl_xor_sync(0xFFFFFFFFu, rs1, 2);
        l_i[0] = l_i[0] * co0 + rs0;
        l_i[1] = l_i[1] * co1 + rs1;

        #pragma unroll
        for (int nt = 0; nt < 8; nt++) {
            acc[nt][0] *= co0; acc[nt][1] *= co0;
            acc[nt][2] *= co1; acc[nt][3] *= co1;
        }

        {
            uint32_t* p0 = Ps + (row0 + g) * PAD + 2 * t;
            uint32_t* p1 = p0 + 8 * PAD;
            #pragma unroll
            for (int nt = 0; nt < 8; nt++) {
                uint2 w0 = {f2tf32(s[nt][0]), f2tf32(s[nt][1])};
                uint2 w1 = {f2tf32(s[nt][2]), f2tf32(s[nt][3])};
                *(uint2*)(p0 + nt * 8) = w0;
                *(uint2*)(p1 + nt * 8) = w1;
            }
        }
        __syncthreads();

        #pragma unroll
        for (int ks = 0; ks < 8; ks++) {
            const uint32_t* pa = Ps + (row0 + g) * PAD + ks * 8 + t;
            uint32_t a[4] = {pa[0], pa[8 * PAD], pa[4], pa[8 * PAD + 4]};
            #pragma unroll
            for (int nt = 0; nt < 8; nt++) {
                const uint32_t* pb = Vt + (nt * 8 + g) * PAD + ks * 8 + t;
                uint32_t b[2] = {pb[0], pb[4]};
                mma_tf32(acc[nt], a, b);
            }
        }
    }

    const float inv0 = 1.0f / l_i[0];
    const float inv1 = 1.0f / l_i[1];
    float* O0 = g_AO + headbase + (size_t)(qb0 + row0 + g) * D_MODEL;
    float* O1 = O0 + 8 * D_MODEL;
    #pragma unroll
    for (int nt = 0; nt < 8; nt++) {
        const int c = nt * 8 + 2 * t;
        float2 v0 = {acc[nt][0] * inv0, acc[nt][1] * inv0};
        float2 v1 = {acc[nt][2] * inv1, acc[nt][3] * inv1};
        *(float2*)(O0 + c) = v0;
        *(float2*)(O1 + c) = v1;
    }
}

// ---------------------------------------------------------------------------
// Launch
// ---------------------------------------------------------------------------
extern "C" void kernel_launch(void* const* d_in, const int* in_sizes, int n_in,
                              void* d_out, int out_size)
{
    const float* X  = (const float*)d_in[0];
    const float* Wq = (const float*)d_in[1];
    const float* bq = (const float*)d_in[2];
    const float* Wk = (const float*)d_in[3];
    const float* bk = (const float*)d_in[4];
    const float* Wv = (const float*)d_in[5];
    const float* bv = (const float*)d_in[6];
    const float* Wo = (const float*)d_in[7];
    const float* bo = (const float*)d_in[8];
    float* out = (float*)d_out;

    cudaFuncSetAttribute(gemm_qkv, cudaFuncAttributeMaxDynamicSharedMemorySize,
                         GEMM_SMEM_BYTES);
    cudaFuncSetAttribute(gemm_out, cudaFuncAttributeMaxDynamicSharedMemorySize,
                         GEMM_SMEM_BYTES);
    cudaFuncSetAttribute(attn_mma, cudaFuncAttributeMaxDynamicSharedMemorySize,
                         ATTN_SMEM_BYTES);

    dim3 qkv_grid(D_MODEL / 64, NTOK / 128, 3);   // (16, 32, 3)
    dim3 out_grid(D_MODEL / 64, NTOK / 128);      // (16, 32)

    gemm_qkv<<<qkv_grid, 256, GEMM_SMEM_BYTES>>>(X, Wq, bq, Wk, bk, Wv, bv);

    attn_mma<<<dim3(S_LEN / QT, NH, NBATCH), 256, ATTN_SMEM_BYTES>>>();

    gemm_out<<<out_grid, 256, GEMM_SMEM_BYTES>>>(Wo, bo, out);
}

// round 9
// speedup vs baseline: 1.4080x; 1.4080x over previous
#include <cuda_runtime.h>
#include <cuda_fp16.h>
#include <cstdint>

// Problem constants
#define D_MODEL 1024
#define S_LEN   2048
#define NH      16
#define HDIM    64
#define NBATCH  2
#define NTOK    (NBATCH * S_LEN)   // 4096

// Scratch (static __device__ globals — allocation-free per harness rules)
__device__ float g_Q [NTOK * D_MODEL];
__device__ float g_K [NTOK * D_MODEL];
__device__ float g_V [NTOK * D_MODEL];
__device__ float g_AO[NTOK * D_MODEL];

// ---------------------------------------------------------------------------
// Helpers (legacy tensor-core path — tcgen05 rejected by sm_100 PTX target).
// ---------------------------------------------------------------------------
__device__ __forceinline__ uint32_t f2h2(float lo, float hi) {
    __half2 h = __floats2half2_rn(lo, hi);
    return *(uint32_t*)&h;
}
// D[16x8] += A[16x16] * B[16x8], fp16 inputs, fp32 accumulate.
__device__ __forceinline__ void mma_f16(float* d, const uint32_t* a, const uint32_t* b) {
    asm volatile(
        "mma.sync.aligned.m16n8k16.row.col.f32.f16.f16.f32 "
        "{%0,%1,%2,%3}, {%4,%5,%6,%7}, {%8,%9}, {%0,%1,%2,%3};"
        : "+f"(d[0]), "+f"(d[1]), "+f"(d[2]), "+f"(d[3])
        : "r"(a[0]), "r"(a[1]), "r"(a[2]), "r"(a[3]), "r"(b[0]), "r"(b[1]));
}

// ===========================================================================
// fp16 tensor-core GEMM: C[m][n] = sum_k A[m][k]*B[n][k] + bias[n]
// 128(M) x 64(N) CTA tile, k-stage 32 (= 16 half2 words/row, padded to 20),
// double-buffered smem, 256 threads, 8 warps 4x2, warp tile 32x32.
// 2 k16-steps x 8 mma per stage (half the instruction count of tf32-k8).
// ===========================================================================
#define ROWW 20                                   // words/row: 16 data + 4 pad
#define STG_WORDS_AB (192 * ROWW)                 // A(128) + B(64) rows
#define GEMM_SMEM_BYTES (2 * STG_WORDS_AB * 4)    // 30720 B

__device__ __forceinline__ void gemm_tile_body(
    const float* __restrict__ A, const float* __restrict__ B,
    const float* __restrict__ bias, float* __restrict__ C,
    int bM, int bN, uint32_t* sm)
{
    const int tid  = threadIdx.x;
    const int lane = tid & 31;
    const int wid  = tid >> 5;
    const int g    = lane >> 2;
    const int t    = lane & 3;
    const int wm   = (wid >> 1) * 32;   // warp m-base
    const int wn   = (wid & 1) * 32;    // warp n-base

    // Staging: A = 128x32 fp32 (4 float4/thread), B = 64x32 (2 float4/thread).
    const int c4 = tid & 7;             // float4 column (covers 32 floats/row)
    const int rA = tid >> 3;            // base row 0..31
    const float* gA = A + (size_t)(bM + rA) * D_MODEL + c4 * 4;
    const float* gB = B + (size_t)(bN + rA) * D_MODEL + c4 * 4;
    const int so = rA * ROWW + c4 * 2;  // word offset (2 words per float4)

    float acc[8][4];
    #pragma unroll
    for (int i = 0; i < 8; i++)
        #pragma unroll
        for (int j = 0; j < 4; j++) acc[i][j] = 0.0f;

    // Prologue: stage 0 -> buffer 0.
    {
        uint32_t* dA = sm;
        uint32_t* dB = sm + 128 * ROWW;
        #pragma unroll
        for (int i = 0; i < 4; i++) {
            float4 v = *(const float4*)(gA + (size_t)i * 32 * D_MODEL);
            uint2 w = {f2h2(v.x, v.y), f2h2(v.z, v.w)};
            *(uint2*)(dA + so + i * 32 * ROWW) = w;
        }
        #pragma unroll
        for (int i = 0; i < 2; i++) {
            float4 v = *(const float4*)(gB + (size_t)i * 32 * D_MODEL);
            uint2 w = {f2h2(v.x, v.y), f2h2(v.z, v.w)};
            *(uint2*)(dB + so + i * 32 * ROWW) = w;
        }
    }
    __syncthreads();

    for (int s = 0; s < 32; s++) {
        const uint32_t* bufA = sm + (s & 1) * STG_WORDS_AB;
        const uint32_t* bufB = bufA + 128 * ROWW;

        // Register prefetch of next stage.
        float4 ra[4], rb[2];
        if (s + 1 < 32) {
            const int kt = (s + 1) * 32;
            #pragma unroll
            for (int i = 0; i < 4; i++)
                ra[i] = *(const float4*)(gA + (size_t)i * 32 * D_MODEL + kt);
            #pragma unroll
            for (int i = 0; i < 2; i++)
                rb[i] = *(const float4*)(gB + (size_t)i * 32 * D_MODEL + kt);
        }

        // Compute: 2 k16-steps, 8 mma each (2 m-tiles x 4 n-tiles).
        const uint32_t* pA = bufA + (wm + g) * ROWW + t;
        const uint32_t* pB = bufB + (wn + g) * ROWW + t;
        #pragma unroll
        for (int ks = 0; ks < 2; ks++) {
            const int k0 = ks * 8;      // word offset of this k16 group
            uint32_t af[2][4], bf[4][2];
            #pragma unroll
            for (int i = 0; i < 2; i++) {
                af[i][0] = pA[(i * 16 + 0) * ROWW + k0];
                af[i][1] = pA[(i * 16 + 8) * ROWW + k0];
                af[i][2] = pA[(i * 16 + 0) * ROWW + k0 + 4];
                af[i][3] = pA[(i * 16 + 8) * ROWW + k0 + 4];
            }
            #pragma unroll
            for (int j = 0; j < 4; j++) {
                bf[j][0] = pB[j * 8 * ROWW + k0];
                bf[j][1] = pB[j * 8 * ROWW + k0 + 4];
            }
            #pragma unroll
            for (int i = 0; i < 2; i++)
                #pragma unroll
                for (int j = 0; j < 4; j++)
                    mma_f16(acc[i * 4 + j], af[i], bf[j]);
        }

        // Store prefetched stage into the other buffer.
        if (s + 1 < 32) {
            uint32_t* dA = sm + ((s + 1) & 1) * STG_WORDS_AB;
            uint32_t* dB = dA + 128 * ROWW;
            #pragma unroll
            for (int i = 0; i < 4; i++) {
                uint2 w = {f2h2(ra[i].x, ra[i].y), f2h2(ra[i].z, ra[i].w)};
                *(uint2*)(dA + so + i * 32 * ROWW) = w;
            }
            #pragma unroll
            for (int i = 0; i < 2; i++) {
                uint2 w = {f2h2(rb[i].x, rb[i].y), f2h2(rb[i].z, rb[i].w)};
                *(uint2*)(dB + so + i * 32 * ROWW) = w;
            }
        }
        __syncthreads();
    }

    // Epilogue: bias + float2 stores.
    #pragma unroll
    for (int i = 0; i < 2; i++) {
        const int m0 = bM + wm + i * 16 + g;
        #pragma unroll
        for (int j = 0; j < 4; j++) {
            const int col = bN + wn + j * 8 + 2 * t;
            float2 bb = *(const float2*)(bias + col);
            float2 v0 = {acc[i * 4 + j][0] + bb.x, acc[i * 4 + j][1] + bb.y};
            float2 v1 = {acc[i * 4 + j][2] + bb.x, acc[i * 4 + j][3] + bb.y};
            *(float2*)(C + (size_t)m0 * D_MODEL + col)       = v0;
            *(float2*)(C + (size_t)(m0 + 8) * D_MODEL + col) = v1;
        }
    }
}

// Fused QKV: gridDim.z selects projection.
__global__ __launch_bounds__(256, 2)
void gemm_qkv(const float* __restrict__ X,
              const float* __restrict__ Wq, const float* __restrict__ bq,
              const float* __restrict__ Wk, const float* __restrict__ bk,
              const float* __restrict__ Wv, const float* __restrict__ bv)
{
    extern __shared__ uint32_t sm[];
    const float* B;  const float* bias;  float* C;
    if (blockIdx.z == 0)      { B = Wq; bias = bq; C = g_Q; }
    else if (blockIdx.z == 1) { B = Wk; bias = bk; C = g_K; }
    else                      { B = Wv; bias = bv; C = g_V; }
    gemm_tile_body(X, B, bias, C, blockIdx.y * 128, blockIdx.x * 64, sm);
}

__global__ __launch_bounds__(256, 2)
void gemm_out(const float* __restrict__ Wo, const float* __restrict__ bo,
              float* __restrict__ out)
{
    extern __shared__ uint32_t sm[];
    gemm_tile_body(g_AO, Wo, bo, out, blockIdx.y * 128, blockIdx.x * 64, sm);
}

// ===========================================================================
// fp16 tensor-core causal flash attention (fp32 softmax/accumulators).
// Same structure as the verified R6 kernel; all operands half2-packed along
// the contraction dim -> 4 k16-steps per 64-wide contraction (was 8 k8).
// Row pitch 36 words (64 halves data + pad): 4g+t mod 32 distinct -> no
// fragment bank conflicts.
// ===========================================================================
#define QT 128
#define KT 64
#define PADW 36
#define ATTN_SMEM_BYTES ((QT + KT + HDIM + QT) * PADW * 4)   // 55296 B

__global__ __launch_bounds__(256, 2)
void attn_mma()
{
    extern __shared__ uint32_t sma[];
    uint32_t* Qs = sma;                  // [128][36w]  Q (pre-scaled, fp16)
    uint32_t* Ks = Qs + QT * PADW;       // [64][36w]   K natural [key][d]
    uint32_t* Vt = Ks + KT * PADW;       // [64][36w]   V transposed [d][key]
    uint32_t* Ps = Vt + HDIM * PADW;     // [128][36w]  P (fp16)
    __half* Vth = (__half*)Vt;           // half view, pitch 72

    const int tid  = threadIdx.x;
    const int lane = tid & 31;
    const int wid  = tid >> 5;
    const int g    = lane >> 2;
    const int t    = lane & 3;
    const int qt   = (int)(gridDim.x - 1) - (int)blockIdx.x;  // heavy tiles first
    const int h    = blockIdx.y;
    const int n    = blockIdx.z;
    const int qb0  = qt * QT;
    const int row0 = wid * 16;

    const size_t headbase = ((size_t)n * S_LEN) * D_MODEL + h * HDIM;

    // Load Q tile, pre-scaled by 1/sqrt(64), packed half2 along d.
    {
        const float* Qg = g_Q + headbase + (size_t)qb0 * D_MODEL;
        #pragma unroll
        for (int i = 0; i < 8; i++) {
            int idx = tid + i * 256;
            int r = idx >> 4, c4 = idx & 15;
            float4 v = *(const float4*)(Qg + (size_t)r * D_MODEL + c4 * 4);
            uint2 w = {f2h2(v.x * 0.125f, v.y * 0.125f),
                       f2h2(v.z * 0.125f, v.w * 0.125f)};
            *(uint2*)(Qs + r * PADW + c4 * 2) = w;
        }
    }

    float m_i[2] = {-1e30f, -1e30f};
    float l_i[2] = {0.0f, 0.0f};
    float acc[8][4];
    #pragma unroll
    for (int i = 0; i < 8; i++)
        #pragma unroll
        for (int j = 0; j < 4; j++) acc[i][j] = 0.0f;

    const int nkb = (qb0 + QT) / KT;

    for (int kb = 0; kb < nkb; kb++) {
        __syncthreads();
        {
            const float* Kg = g_K + headbase + (size_t)kb * KT * D_MODEL;
            const float* Vg = g_V + headbase + (size_t)kb * KT * D_MODEL;
            #pragma unroll
            for (int i = 0; i < 4; i++) {
                int idx = tid + i * 256;
                int r = idx >> 4, c4 = idx & 15;
                float4 kv = *(const float4*)(Kg + (size_t)r * D_MODEL + c4 * 4);
                uint2 kw = {f2h2(kv.x, kv.y), f2h2(kv.z, kv.w)};
                *(uint2*)(Ks + r * PADW + c4 * 2) = kw;
                // V transpose: scalar half stores Vt[d][key]
                int rv = idx & 63, cv = idx >> 6;
                float4 vv = *(const float4*)(Vg + (size_t)rv * D_MODEL + cv * 4);
                Vth[(cv * 4 + 0) * 72 + rv] = __float2half_rn(vv.x);
                Vth[(cv * 4 + 1) * 72 + rv] = __float2half_rn(vv.y);
                Vth[(cv * 4 + 2) * 72 + rv] = __float2half_rn(vv.z);
                Vth[(cv * 4 + 3) * 72 + rv] = __float2half_rn(vv.w);
            }
        }
        __syncthreads();

        // ---- S = (Q/8) K^T : 4 k16-steps x 8 n-tiles ----
        float s[8][4];
        #pragma unroll
        for (int i = 0; i < 8; i++)
            #pragma unroll
            for (int j = 0; j < 4; j++) s[i][j] = 0.0f;

        #pragma unroll
        for (int ks = 0; ks < 4; ks++) {
            const uint32_t* pa = Qs + (row0 + g) * PADW + ks * 8 + t;
            uint32_t a[4] = {pa[0], pa[8 * PADW], pa[4], pa[8 * PADW + 4]};
            #pragma unroll
            for (int nt = 0; nt < 8; nt++) {
                const uint32_t* pb = Ks + (nt * 8 + g) * PADW + ks * 8 + t;
                uint32_t b[2] = {pb[0], pb[4]};
                mma_f16(s[nt], a, b);
            }
        }

        // ---- causal mask ----
        const int r0g = qb0 + row0 + g;
        if ((kb + 1) * KT - 1 > qb0 + row0) {
            #pragma unroll
            for (int nt = 0; nt < 8; nt++) {
                int c = kb * KT + nt * 8 + 2 * t;
                if (c     > r0g)     s[nt][0] = -1e30f;
                if (c + 1 > r0g)     s[nt][1] = -1e30f;
                if (c     > r0g + 8) s[nt][2] = -1e30f;
                if (c + 1 > r0g + 8) s[nt][3] = -1e30f;
            }
        }

        // ---- online softmax (rows g, g+8; quad reduction) ----
        float mx0 = -1e30f, mx1 = -1e30f;
        #pragma unroll
        for (int nt = 0; nt < 8; nt++) {
            mx0 = fmaxf(mx0, fmaxf(s[nt][0], s[nt][1]));
            mx1 = fmaxf(mx1, fmaxf(s[nt][2], s[nt][3]));
        }
        mx0 = fmaxf(mx0, __shfl_xor_sync(0xFFFFFFFFu, mx0, 1));
        mx0 = fmaxf(mx0, __shfl_xor_sync(0xFFFFFFFFu, mx0, 2));
        mx1 = fmaxf(mx1, __shfl_xor_sync(0xFFFFFFFFu, mx1, 1));
        mx1 = fmaxf(mx1, __shfl_xor_sync(0xFFFFFFFFu, mx1, 2));

        const float mn0 = fmaxf(m_i[0], mx0);
        const float mn1 = fmaxf(m_i[1], mx1);
        const float co0 = __expf(m_i[0] - mn0);
        const float co1 = __expf(m_i[1] - mn1);
        m_i[0] = mn0; m_i[1] = mn1;

        float rs0 = 0.0f, rs1 = 0.0f;
        #pragma unroll
        for (int nt = 0; nt < 8; nt++) {
            s[nt][0] = __expf(s[nt][0] - mn0);
            s[nt][1] = __expf(s[nt][1] - mn0);
            s[nt][2] = __expf(s[nt][2] - mn1);
            s[nt][3] = __expf(s[nt][3] - mn1);
            rs0 += s[nt][0] + s[nt][1];
            rs1 += s[nt][2] + s[nt][3];
        }
        rs0 += __shfl_xor_sync(0xFFFFFFFFu, rs0, 1);
        rs0 += __shfl_xor_sync(0xFFFFFFFFu, rs0, 2);
        rs1 += __shfl_xor_sync(0xFFFFFFFFu, rs1, 1);
        rs1 += __shfl_xor_sync(0xFFFFFFFFu, rs1, 2);
        l_i[0] = l_i[0] * co0 + rs0;
        l_i[1] = l_i[1] * co1 + rs1;

        #pragma unroll
        for (int nt = 0; nt < 8; nt++) {
            acc[nt][0] *= co0; acc[nt][1] *= co0;
            acc[nt][2] *= co1; acc[nt][3] *= co1;
        }

        // ---- write P (fp16, half2 = one word per key pair) ----
        {
            uint32_t* p0 = Ps + (row0 + g) * PADW + t;
            uint32_t* p1 = p0 + 8 * PADW;
            #pragma unroll
            for (int nt = 0; nt < 8; nt++) {
                p0[nt * 4] = f2h2(s[nt][0], s[nt][1]);
                p1[nt * 4] = f2h2(s[nt][2], s[nt][3]);
            }
        }
        __syncthreads();

        // ---- acc += P V : 4 k16-steps (keys) x 8 n-tiles (d) ----
        #pragma unroll
        for (int ks = 0; ks < 4; ks++) {
            const uint32_t* pa = Ps + (row0 + g) * PADW + ks * 8 + t;
            uint32_t a[4] = {pa[0], pa[8 * PADW], pa[4], pa[8 * PADW + 4]};
            #pragma unroll
            for (int nt = 0; nt < 8; nt++) {
                const uint32_t* pb = Vt + (nt * 8 + g) * PADW + ks * 8 + t;
                uint32_t b[2] = {pb[0], pb[4]};
                mma_f16(acc[nt], a, b);
            }
        }
    }

    // ---- epilogue ----
    const float inv0 = 1.0f / l_i[0];
    const float inv1 = 1.0f / l_i[1];
    float* O0 = g_AO + headbase + (size_t)(qb0 + row0 + g) * D_MODEL;
    float* O1 = O0 + 8 * D_MODEL;
    #pragma unroll
    for (int nt = 0; nt < 8; nt++) {
        const int c = nt * 8 + 2 * t;
        float2 v0 = {acc[nt][0] * inv0, acc[nt][1] * inv0};
        float2 v1 = {acc[nt][2] * inv1, acc[nt][3] * inv1};
        *(float2*)(O0 + c) = v0;
        *(float2*)(O1 + c) = v1;
    }
}

// ---------------------------------------------------------------------------
// Launch
// ---------------------------------------------------------------------------
extern "C" void kernel_launch(void* const* d_in, const int* in_sizes, int n_in,
                              void* d_out, int out_size)
{
    const float* X  = (const float*)d_in[0];
    const float* Wq = (const float*)d_in[1];
    const float* bq = (const float*)d_in[2];
    const float* Wk = (const float*)d_in[3];
    const float* bk = (const float*)d_in[4];
    const float* Wv = (const float*)d_in[5];
    const float* bv = (const float*)d_in[6];
    const float* Wo = (const float*)d_in[7];
    const float* bo = (const float*)d_in[8];
    float* out = (float*)d_out;

    cudaFuncSetAttribute(gemm_qkv, cudaFuncAttributeMaxDynamicSharedMemorySize,
                         GEMM_SMEM_BYTES);
    cudaFuncSetAttribute(gemm_out, cudaFuncAttributeMaxDynamicSharedMemorySize,
                         GEMM_SMEM_BYTES);
    cudaFuncSetAttribute(attn_mma, cudaFuncAttributeMaxDynamicSharedMemorySize,
                         ATTN_SMEM_BYTES);

    dim3 qkv_grid(D_MODEL / 64, NTOK / 128, 3);   // (16, 32, 3)
    dim3 out_grid(D_MODEL / 64, NTOK / 128);      // (16, 32)

    gemm_qkv<<<qkv_grid, 256, GEMM_SMEM_BYTES>>>(X, Wq, bq, Wk, bk, Wv, bv);

    attn_mma<<<dim3(S_LEN / QT, NH, NBATCH), 256, ATTN_SMEM_BYTES>>>();

    gemm_out<<<out_grid, 256, GEMM_SMEM_BYTES>>>(Wo, bo, out);
}

// round 11
// speedup vs baseline: 1.5669x; 1.1129x over previous
#include <cuda_runtime.h>
#include <cuda_fp16.h>
#include <cstdint>

// Problem constants
#define D_MODEL 1024
#define S_LEN   2048
#define NH      16
#define HDIM    64
#define NBATCH  2
#define NTOK    (NBATCH * S_LEN)   // 4096

// Scratch (static __device__ globals — allocation-free per harness rules)
__device__ float g_Q [NTOK * D_MODEL];
__device__ float g_K [NTOK * D_MODEL];
__device__ float g_V [NTOK * D_MODEL];
__device__ float g_AO[NTOK * D_MODEL];

// ---------------------------------------------------------------------------
// Helpers (legacy tensor-core path — tcgen05 rejected by sm_100 PTX target).
// R11 = byte-for-byte resubmit of R10 (container failure attributed to infra
// flake after full address/layout audit; identical source discriminates).
// ---------------------------------------------------------------------------
__device__ __forceinline__ uint32_t f2h2(float lo, float hi) {
    __half2 h = __floats2half2_rn(lo, hi);
    return *(uint32_t*)&h;
}
__device__ __forceinline__ uint32_t smem_addr_u32(const void* p) {
    return (uint32_t)__cvta_generic_to_shared(p);
}
// D[16x8] += A[16x16] * B[16x8], fp16 inputs, fp32 accumulate.
__device__ __forceinline__ void mma_f16(float* d, const uint32_t* a, const uint32_t* b) {
    asm volatile(
        "mma.sync.aligned.m16n8k16.row.col.f32.f16.f16.f32 "
        "{%0,%1,%2,%3}, {%4,%5,%6,%7}, {%8,%9}, {%0,%1,%2,%3};"
        : "+f"(d[0]), "+f"(d[1]), "+f"(d[2]), "+f"(d[3])
        : "r"(a[0]), "r"(a[1]), "r"(a[2]), "r"(a[3]), "r"(b[0]), "r"(b[1]));
}
// ldmatrix x4: four 8x8 b16 matrices; lanes 0-7/8-15/16-23/24-31 give row
// addresses of matrices 0/1/2/3; lane l ends up with (row l/4, cols 2(l%4)..+1).
__device__ __forceinline__ void ldsm4(uint32_t& r0, uint32_t& r1,
                                      uint32_t& r2, uint32_t& r3, uint32_t addr) {
    asm volatile("ldmatrix.sync.aligned.m8n8.x4.shared.b16 {%0,%1,%2,%3}, [%4];"
                 : "=r"(r0), "=r"(r1), "=r"(r2), "=r"(r3) : "r"(addr));
}

// ===========================================================================
// fp16 tensor-core GEMM: C[m][n] = sum_k A[m][k]*B[n][k] + bias[n]
// 128(M) x 128(N) CTA tile, k-stage 32 (16 half2 words/row, padded to 20),
// double-buffered smem, 256 threads, 8 warps 2x4, warp tile 64x32.
// Fragments via ldmatrix.x4: 6 LDSM + 16 MMA per warp k16-step.
// ===========================================================================
#define ROWW 20                                   // words/row: 16 data + 4 pad
#define STG_WORDS_AB (256 * ROWW)                 // A(128) + B(128) rows
#define GEMM_SMEM_BYTES (2 * STG_WORDS_AB * 4)    // 40960 B

__device__ __forceinline__ void gemm_tile_body(
    const float* __restrict__ A, const float* __restrict__ B,
    const float* __restrict__ bias, float* __restrict__ C,
    int bM, int bN, uint32_t* sm)
{
    const int tid  = threadIdx.x;
    const int lane = tid & 31;
    const int wid  = tid >> 5;
    const int g    = lane >> 2;
    const int t    = lane & 3;
    const int wm   = (wid >> 2) * 64;   // warp m-base (0/64)
    const int wn   = (wid & 3) * 32;    // warp n-base (0/32/64/96)

    // ldmatrix lane base: row (lane&15), k-half select (lane>>4)*4 words.
    const uint32_t smu = smem_addr_u32(sm);
    const uint32_t aLane = smu + (((lane & 15) * ROWW + ((lane >> 4) << 2)) << 2);
    const uint32_t bLane = aLane + (128 * ROWW << 2);

    // Staging: A,B each 128 rows x 32 fp32 -> 4 float4/thread each.
    const int c4 = tid & 7;
    const int rA = tid >> 3;            // base row 0..31 (rows rA + i*32)
    const float* gA = A + (size_t)(bM + rA) * D_MODEL + c4 * 4;
    const float* gB = B + (size_t)(bN + rA) * D_MODEL + c4 * 4;
    const int so = rA * ROWW + c4 * 2;

    float acc[16][4];
    #pragma unroll
    for (int i = 0; i < 16; i++)
        #pragma unroll
        for (int j = 0; j < 4; j++) acc[i][j] = 0.0f;

    // Prologue: stage 0 -> buffer 0.
    {
        uint32_t* dA = sm;
        uint32_t* dB = sm + 128 * ROWW;
        #pragma unroll
        for (int i = 0; i < 4; i++) {
            float4 va = *(const float4*)(gA + (size_t)i * 32 * D_MODEL);
            float4 vb = *(const float4*)(gB + (size_t)i * 32 * D_MODEL);
            uint2 wa = {f2h2(va.x, va.y), f2h2(va.z, va.w)};
            uint2 wb = {f2h2(vb.x, vb.y), f2h2(vb.z, vb.w)};
            *(uint2*)(dA + so + i * 32 * ROWW) = wa;
            *(uint2*)(dB + so + i * 32 * ROWW) = wb;
        }
    }
    __syncthreads();

    for (int s = 0; s < 32; s++) {
        const uint32_t bufByte = (uint32_t)(s & 1) * (STG_WORDS_AB << 2);

        // Register prefetch of next stage.
        float4 ra[4], rb[4];
        if (s + 1 < 32) {
            const int kt = (s + 1) * 32;
            #pragma unroll
            for (int i = 0; i < 4; i++) {
                ra[i] = *(const float4*)(gA + (size_t)i * 32 * D_MODEL + kt);
                rb[i] = *(const float4*)(gB + (size_t)i * 32 * D_MODEL + kt);
            }
        }

        // Compute: 2 k16-steps; per step 4 A-ldsm + 2 B-ldsm + 16 mma.
        #pragma unroll
        for (int ks = 0; ks < 2; ks++) {
            const uint32_t kByte = bufByte + ks * 32;   // ks*8 words
            uint32_t af[4][4];
            #pragma unroll
            for (int i = 0; i < 4; i++)
                ldsm4(af[i][0], af[i][1], af[i][2], af[i][3],
                      aLane + kByte + (((wm + i * 16) * ROWW) << 2));
            #pragma unroll
            for (int j = 0; j < 2; j++) {
                uint32_t m0, m1, m2, m3;
                ldsm4(m0, m1, m2, m3,
                      bLane + kByte + (((wn + j * 16) * ROWW) << 2));
                uint32_t b0[2] = {m0, m2}, b1[2] = {m1, m3};
                #pragma unroll
                for (int i = 0; i < 4; i++) {
                    mma_f16(acc[i * 4 + 2 * j],     af[i], b0);
                    mma_f16(acc[i * 4 + 2 * j + 1], af[i], b1);
                }
            }
        }

        // Store prefetched stage into the other buffer.
        if (s + 1 < 32) {
            uint32_t* dA = sm + ((s + 1) & 1) * STG_WORDS_AB;
            uint32_t* dB = dA + 128 * ROWW;
            #pragma unroll
            for (int i = 0; i < 4; i++) {
                uint2 wa = {f2h2(ra[i].x, ra[i].y), f2h2(ra[i].z, ra[i].w)};
                uint2 wb = {f2h2(rb[i].x, rb[i].y), f2h2(rb[i].z, rb[i].w)};
                *(uint2*)(dA + so + i * 32 * ROWW) = wa;
                *(uint2*)(dB + so + i * 32 * ROWW) = wb;
            }
        }
        __syncthreads();
    }

    // Epilogue: bias + float2 stores.
    #pragma unroll
    for (int i = 0; i < 4; i++) {
        const int m0 = bM + wm + i * 16 + g;
        #pragma unroll
        for (int j = 0; j < 4; j++) {
            const int col = bN + wn + j * 8 + 2 * t;
            float2 bb = *(const float2*)(bias + col);
            float2 v0 = {acc[i * 4 + j][0] + bb.x, acc[i * 4 + j][1] + bb.y};
            float2 v1 = {acc[i * 4 + j][2] + bb.x, acc[i * 4 + j][3] + bb.y};
            *(float2*)(C + (size_t)m0 * D_MODEL + col)       = v0;
            *(float2*)(C + (size_t)(m0 + 8) * D_MODEL + col) = v1;
        }
    }
}

// Fused QKV: gridDim.z selects projection.
__global__ __launch_bounds__(256, 1)
void gemm_qkv(const float* __restrict__ X,
              const float* __restrict__ Wq, const float* __restrict__ bq,
              const float* __restrict__ Wk, const float* __restrict__ bk,
              const float* __restrict__ Wv, const float* __restrict__ bv)
{
    extern __shared__ uint32_t sm[];
    const float* B;  const float* bias;  float* C;
    if (blockIdx.z == 0)      { B = Wq; bias = bq; C = g_Q; }
    else if (blockIdx.z == 1) { B = Wk; bias = bk; C = g_K; }
    else                      { B = Wv; bias = bv; C = g_V; }
    gemm_tile_body(X, B, bias, C, blockIdx.y * 128, blockIdx.x * 128, sm);
}

__global__ __launch_bounds__(256, 1)
void gemm_out(const float* __restrict__ Wo, const float* __restrict__ bo,
              float* __restrict__ out)
{
    extern __shared__ uint32_t sm[];
    gemm_tile_body(g_AO, Wo, bo, out, blockIdx.y * 128, blockIdx.x * 128, sm);
}

// ===========================================================================
// fp16 tensor-core causal flash attention (fp32 softmax), ldmatrix fragments.
// ===========================================================================
#define QT 128
#define KT 64
#define PADW 36
#define ATTN_SMEM_BYTES ((QT + KT + HDIM + QT) * PADW * 4)   // 55296 B

__global__ __launch_bounds__(256, 2)
void attn_mma()
{
    extern __shared__ uint32_t sma[];
    uint32_t* Qs = sma;                  // [128][36w]  Q (pre-scaled, fp16)
    uint32_t* Ks = Qs + QT * PADW;       // [64][36w]   K natural [key][d]
    uint32_t* Vt = Ks + KT * PADW;       // [64][36w]   V transposed [d][key]
    uint32_t* Ps = Vt + HDIM * PADW;     // [128][36w]  P (fp16)
    __half* Vth = (__half*)Vt;           // half view, pitch 72

    const int tid  = threadIdx.x;
    const int lane = tid & 31;
    const int wid  = tid >> 5;
    const int g    = lane >> 2;
    const int t    = lane & 3;
    const int qt   = (int)(gridDim.x - 1) - (int)blockIdx.x;  // heavy tiles first
    const int h    = blockIdx.y;
    const int n    = blockIdx.z;
    const int qb0  = qt * QT;
    const int row0 = wid * 16;

    // ldmatrix lane bases (row lane&15, k-half (lane>>4)*4 words).
    const uint32_t laneOfs = (((lane & 15) * PADW + ((lane >> 4) << 2)) << 2);
    const uint32_t qLane = smem_addr_u32(Qs) + laneOfs + ((row0 * PADW) << 2);
    const uint32_t kLane = smem_addr_u32(Ks) + laneOfs;
    const uint32_t vLane = smem_addr_u32(Vt) + laneOfs;
    const uint32_t pLane = smem_addr_u32(Ps) + laneOfs + ((row0 * PADW) << 2);

    const size_t headbase = ((size_t)n * S_LEN) * D_MODEL + h * HDIM;

    // Load Q tile, pre-scaled by 1/sqrt(64), packed half2 along d.
    {
        const float* Qg = g_Q + headbase + (size_t)qb0 * D_MODEL;
        #pragma unroll
        for (int i = 0; i < 8; i++) {
            int idx = tid + i * 256;
            int r = idx >> 4, c4 = idx & 15;
            float4 v = *(const float4*)(Qg + (size_t)r * D_MODEL + c4 * 4);
            uint2 w = {f2h2(v.x * 0.125f, v.y * 0.125f),
                       f2h2(v.z * 0.125f, v.w * 0.125f)};
            *(uint2*)(Qs + r * PADW + c4 * 2) = w;
        }
    }

    float m_i[2] = {-1e30f, -1e30f};
    float l_i[2] = {0.0f, 0.0f};
    float acc[8][4];
    #pragma unroll
    for (int i = 0; i < 8; i++)
        #pragma unroll
        for (int j = 0; j < 4; j++) acc[i][j] = 0.0f;

    const int nkb = (qb0 + QT) / KT;

    for (int kb = 0; kb < nkb; kb++) {
        __syncthreads();
        {
            const float* Kg = g_K + headbase + (size_t)kb * KT * D_MODEL;
            const float* Vg = g_V + headbase + (size_t)kb * KT * D_MODEL;
            #pragma unroll
            for (int i = 0; i < 4; i++) {
                int idx = tid + i * 256;
                int r = idx >> 4, c4 = idx & 15;
                float4 kv = *(const float4*)(Kg + (size_t)r * D_MODEL + c4 * 4);
                uint2 kw = {f2h2(kv.x, kv.y), f2h2(kv.z, kv.w)};
                *(uint2*)(Ks + r * PADW + c4 * 2) = kw;
                int rv = idx & 63, cv = idx >> 6;
                float4 vv = *(const float4*)(Vg + (size_t)rv * D_MODEL + cv * 4);
                Vth[(cv * 4 + 0) * 72 + rv] = __float2half_rn(vv.x);
                Vth[(cv * 4 + 1) * 72 + rv] = __float2half_rn(vv.y);
                Vth[(cv * 4 + 2) * 72 + rv] = __float2half_rn(vv.z);
                Vth[(cv * 4 + 3) * 72 + rv] = __float2half_rn(vv.w);
            }
        }
        __syncthreads();

        // ---- S = (Q/8) K^T : 4 k16-steps x 8 n-tiles ----
        float s[8][4];
        #pragma unroll
        for (int i = 0; i < 8; i++)
            #pragma unroll
            for (int j = 0; j < 4; j++) s[i][j] = 0.0f;

        #pragma unroll
        for (int ks = 0; ks < 4; ks++) {
            const uint32_t kByte = ks * 32;
            uint32_t a[4];
            ldsm4(a[0], a[1], a[2], a[3], qLane + kByte);
            #pragma unroll
            for (int j = 0; j < 4; j++) {
                uint32_t m0, m1, m2, m3;
                ldsm4(m0, m1, m2, m3, kLane + kByte + (((j * 16) * PADW) << 2));
                uint32_t b0[2] = {m0, m2}, b1[2] = {m1, m3};
                mma_f16(s[2 * j],     a, b0);
                mma_f16(s[2 * j + 1], a, b1);
            }
        }

        // ---- causal mask ----
        const int r0g = qb0 + row0 + g;
        if ((kb + 1) * KT - 1 > qb0 + row0) {
            #pragma unroll
            for (int nt = 0; nt < 8; nt++) {
                int c = kb * KT + nt * 8 + 2 * t;
                if (c     > r0g)     s[nt][0] = -1e30f;
                if (c + 1 > r0g)     s[nt][1] = -1e30f;
                if (c     > r0g + 8) s[nt][2] = -1e30f;
                if (c + 1 > r0g + 8) s[nt][3] = -1e30f;
            }
        }

        // ---- online softmax (rows g, g+8; quad reduction) ----
        float mx0 = -1e30f, mx1 = -1e30f;
        #pragma unroll
        for (int nt = 0; nt < 8; nt++) {
            mx0 = fmaxf(mx0, fmaxf(s[nt][0], s[nt][1]));
            mx1 = fmaxf(mx1, fmaxf(s[nt][2], s[nt][3]));
        }
        mx0 = fmaxf(mx0, __shfl_xor_sync(0xFFFFFFFFu, mx0, 1));
        mx0 = fmaxf(mx0, __shfl_xor_sync(0xFFFFFFFFu, mx0, 2));
        mx1 = fmaxf(mx1, __shfl_xor_sync(0xFFFFFFFFu, mx1, 1));
        mx1 = fmaxf(mx1, __shfl_xor_sync(0xFFFFFFFFu, mx1, 2));

        const float mn0 = fmaxf(m_i[0], mx0);
        const float mn1 = fmaxf(m_i[1], mx1);
        const float co0 = __expf(m_i[0] - mn0);
        const float co1 = __expf(m_i[1] - mn1);
        m_i[0] = mn0; m_i[1] = mn1;

        float rs0 = 0.0f, rs1 = 0.0f;
        #pragma unroll
        for (int nt = 0; nt < 8; nt++) {
            s[nt][0] = __expf(s[nt][0] - mn0);
            s[nt][1] = __expf(s[nt][1] - mn0);
            s[nt][2] = __expf(s[nt][2] - mn1);
            s[nt][3] = __expf(s[nt][3] - mn1);
            rs0 += s[nt][0] + s[nt][1];
            rs1 += s[nt][2] + s[nt][3];
        }
        rs0 += __shfl_xor_sync(0xFFFFFFFFu, rs0, 1);
        rs0 += __shfl_xor_sync(0xFFFFFFFFu, rs0, 2);
        rs1 += __shfl_xor_sync(0xFFFFFFFFu, rs1, 1);
        rs1 += __shfl_xor_sync(0xFFFFFFFFu, rs1, 2);
        l_i[0] = l_i[0] * co0 + rs0;
        l_i[1] = l_i[1] * co1 + rs1;

        #pragma unroll
        for (int nt = 0; nt < 8; nt++) {
            acc[nt][0] *= co0; acc[nt][1] *= co0;
            acc[nt][2] *= co1; acc[nt][3] *= co1;
        }

        // ---- write P (fp16 half2 words) ----
        {
            uint32_t* p0 = Ps + (row0 + g) * PADW + t;
            uint32_t* p1 = p0 + 8 * PADW;
            #pragma unroll
            for (int nt = 0; nt < 8; nt++) {
                p0[nt * 4] = f2h2(s[nt][0], s[nt][1]);
                p1[nt * 4] = f2h2(s[nt][2], s[nt][3]);
            }
        }
        __syncthreads();

        // ---- acc += P V : 4 k16-steps (keys) x 8 n-tiles (d) ----
        #pragma unroll
        for (int ks = 0; ks < 4; ks++) {
            const uint32_t kByte = ks * 32;
            uint32_t a[4];
            ldsm4(a[0], a[1], a[2], a[3], pLane + kByte);
            #pragma unroll
            for (int j = 0; j < 4; j++) {
                uint32_t m0, m1, m2, m3;
                ldsm4(m0, m1, m2, m3, vLane + kByte + (((j * 16) * PADW) << 2));
                uint32_t b0[2] = {m0, m2}, b1[2] = {m1, m3};
                mma_f16(acc[2 * j],     a, b0);
                mma_f16(acc[2 * j + 1], a, b1);
            }
        }
    }

    // ---- epilogue ----
    const float inv0 = 1.0f / l_i[0];
    const float inv1 = 1.0f / l_i[1];
    float* O0 = g_AO + headbase + (size_t)(qb0 + row0 + g) * D_MODEL;
    float* O1 = O0 + 8 * D_MODEL;
    #pragma unroll
    for (int nt = 0; nt < 8; nt++) {
        const int c = nt * 8 + 2 * t;
        float2 v0 = {acc[nt][0] * inv0, acc[nt][1] * inv0};
        float2 v1 = {acc[nt][2] * inv1, acc[nt][3] * inv1};
        *(float2*)(O0 + c) = v0;
        *(float2*)(O1 + c) = v1;
    }
}

// ---------------------------------------------------------------------------
// Launch
// ---------------------------------------------------------------------------
extern "C" void kernel_launch(void* const* d_in, const int* in_sizes, int n_in,
                              void* d_out, int out_size)
{
    const float* X  = (const float*)d_in[0];
    const float* Wq = (const float*)d_in[1];
    const float* bq = (const float*)d_in[2];
    const float* Wk = (const float*)d_in[3];
    const float* bk = (const float*)d_in[4];
    const float* Wv = (const float*)d_in[5];
    const float* bv = (const float*)d_in[6];
    const float* Wo = (const float*)d_in[7];
    const float* bo = (const float*)d_in[8];
    float* out = (float*)d_out;

    cudaFuncSetAttribute(gemm_qkv, cudaFuncAttributeMaxDynamicSharedMemorySize,
                         GEMM_SMEM_BYTES);
    cudaFuncSetAttribute(gemm_out, cudaFuncAttributeMaxDynamicSharedMemorySize,
                         GEMM_SMEM_BYTES);
    cudaFuncSetAttribute(attn_mma, cudaFuncAttributeMaxDynamicSharedMemorySize,
                         ATTN_SMEM_BYTES);

    dim3 qkv_grid(D_MODEL / 128, NTOK / 128, 3);  // (8, 32, 3)
    dim3 out_grid(D_MODEL / 128, NTOK / 128);     // (8, 32)

    gemm_qkv<<<qkv_grid, 256, GEMM_SMEM_BYTES>>>(X, Wq, bq, Wk, bk, Wv, bv);

    attn_mma<<<dim3(S_LEN / QT, NH, NBATCH), 256, ATTN_SMEM_BYTES>>>();

    gemm_out<<<out_grid, 256, GEMM_SMEM_BYTES>>>(Wo, bo, out);
}

// round 13
// speedup vs baseline: 1.8129x; 1.1569x over previous
#include <cuda_runtime.h>
#include <cuda_fp16.h>
#include <cstdint>

// Problem constants
#define D_MODEL 1024
#define S_LEN   2048
#define NH      16
#define HDIM    64
#define NBATCH  2
#define NTOK    (NBATCH * S_LEN)   // 4096
#define DD      (D_MODEL * D_MODEL)

// Scratch (static __device__ globals — allocation-free per harness rules)
__device__ __half g_Xh [NTOK * D_MODEL];
__device__ __half g_Wh [4 * DD];            // Wq, Wk, Wv, Wo (fp16)
__device__ __half g_Qh [NTOK * D_MODEL];    // pre-scaled by 1/8
__device__ __half g_Kh [NTOK * D_MODEL];
__device__ __half g_Vh [NTOK * D_MODEL];
__device__ __half g_AOh[NTOK * D_MODEL];

// ---------------------------------------------------------------------------
// Helpers (legacy tensor-core path — tcgen05 rejected by sm_100 PTX target).
// R13 = byte-identical resubmit of R12: full pipeline/address audit found no
// fault; failure signature matches the R10 infra flake (R11 identical-source
// resubmit passed). Identical source keeps attribution clean.
// ---------------------------------------------------------------------------
__device__ __forceinline__ uint32_t f2h2(float lo, float hi) {
    __half2 h = __floats2half2_rn(lo, hi);
    return *(uint32_t*)&h;
}
__device__ __forceinline__ uint32_t smem_addr_u32(const void* p) {
    return (uint32_t)__cvta_generic_to_shared(p);
}
__device__ __forceinline__ void mma_f16(float* d, const uint32_t* a, const uint32_t* b) {
    asm volatile(
        "mma.sync.aligned.m16n8k16.row.col.f32.f16.f16.f32 "
        "{%0,%1,%2,%3}, {%4,%5,%6,%7}, {%8,%9}, {%0,%1,%2,%3};"
        : "+f"(d[0]), "+f"(d[1]), "+f"(d[2]), "+f"(d[3])
        : "r"(a[0]), "r"(a[1]), "r"(a[2]), "r"(a[3]), "r"(b[0]), "r"(b[1]));
}
__device__ __forceinline__ void ldsm4(uint32_t& r0, uint32_t& r1,
                                      uint32_t& r2, uint32_t& r3, uint32_t addr) {
    asm volatile("ldmatrix.sync.aligned.m8n8.x4.shared.b16 {%0,%1,%2,%3}, [%4];"
                 : "=r"(r0), "=r"(r1), "=r"(r2), "=r"(r3) : "r"(addr));
}
__device__ __forceinline__ void cp16(uint32_t dst, const void* src) {
    asm volatile("cp.async.cg.shared.global [%0], [%1], 16;" :: "r"(dst), "l"(src));
}
__device__ __forceinline__ void cp_commit() {
    asm volatile("cp.async.commit_group;" ::: "memory");
}
__device__ __forceinline__ void cp_wait1() {
    asm volatile("cp.async.wait_group 1;" ::: "memory");
}
__device__ __forceinline__ void cp_wait0() {
    asm volatile("cp.async.wait_group 0;" ::: "memory");
}

// ===========================================================================
// fp32 -> fp16 conversion (X + 4 weight matrices), one pass per launch.
// ===========================================================================
__global__ void convert_fp16(const float* __restrict__ X,
                             const float* __restrict__ Wq, const float* __restrict__ Wk,
                             const float* __restrict__ Wv, const float* __restrict__ Wo)
{
    const float* src; __half* dst; uint32_t n4;
    switch (blockIdx.z) {
        case 0:  src = X;  dst = g_Xh;          n4 = NTOK * D_MODEL / 4; break;
        case 1:  src = Wq; dst = g_Wh;          n4 = DD / 4; break;
        case 2:  src = Wk; dst = g_Wh + DD;     n4 = DD / 4; break;
        case 3:  src = Wv; dst = g_Wh + 2 * DD; n4 = DD / 4; break;
        default: src = Wo; dst = g_Wh + 3 * DD; n4 = DD / 4; break;
    }
    for (uint32_t i = blockIdx.x * blockDim.x + threadIdx.x; i < n4;
         i += gridDim.x * blockDim.x) {
        float4 v = ((const float4*)src)[i];
        uint2 w = {f2h2(v.x, v.y), f2h2(v.z, v.w)};
        ((uint2*)dst)[i] = w;
    }
}

// ===========================================================================
// fp16 tensor-core GEMM with cp.async 3-stage pipeline.
// C[m][n] = (sum_k A[m][k]*B[n][k] + bias[n]) * scale
// 128x128 CTA tile, k-stage 32, 256 threads, 8 warps 2x4, warp tile 64x32.
// Smem rows: 32 halves data (64B) + 16B pad = 80B pitch (ldmatrix
// conflict-free; cp.async writes 4x16B chunks per row).
// ===========================================================================
#define ROWB 80
#define STG_BYTES (256 * ROWB)                  // A(128 rows) + B(128 rows)
#define GEMM_SMEM_BYTES (3 * STG_BYTES)         // 61440 B

template <bool HALF_OUT, typename OutT>
__device__ __forceinline__ void gemm_body(
    const __half* __restrict__ A, const __half* __restrict__ B,
    const float* __restrict__ bias, OutT* __restrict__ C,
    int bM, int bN, float scale, void* smv)
{
    const int tid  = threadIdx.x;
    const int lane = tid & 31;
    const int wid  = tid >> 5;
    const int g    = lane >> 2;
    const int t    = lane & 3;
    const int wm   = (wid >> 2) * 64;
    const int wn   = (wid & 3) * 32;

    const uint32_t smu = smem_addr_u32(smv);
    // ldmatrix lane base: row (lane&15), k-half select (lane>>4)*16 bytes.
    const uint32_t aLane = smu + (lane & 15) * ROWB + ((lane >> 4) << 4);
    const uint32_t bLane = aLane + 128 * ROWB;

    // cp.async staging: idx in [0,512): r=idx>>2 (row), ch=idx&3 (16B chunk).
    const int ch = tid & 3;
    const int rr = tid >> 2;            // rows rr and rr+64
    const __half* sA0 = A + (size_t)(bM + rr) * D_MODEL + ch * 8;
    const __half* sA1 = sA0 + (size_t)64 * D_MODEL;
    const __half* sB0 = B + (size_t)(bN + rr) * D_MODEL + ch * 8;
    const __half* sB1 = sB0 + (size_t)64 * D_MODEL;
    const uint32_t dA0 = rr * ROWB + ch * 16;
    const uint32_t dA1 = dA0 + 64 * ROWB;
    const uint32_t dB0 = dA0 + 128 * ROWB;
    const uint32_t dB1 = dB0 + 64 * ROWB;

    float acc[16][4];
    #pragma unroll
    for (int i = 0; i < 16; i++)
        #pragma unroll
        for (int j = 0; j < 4; j++) acc[i][j] = 0.0f;

    // Prologue: issue stages 0 and 1.
    #pragma unroll
    for (int s = 0; s < 2; s++) {
        const uint32_t sb = smu + s * STG_BYTES;
        const int kt = s * 32;
        cp16(sb + dA0, sA0 + kt);
        cp16(sb + dA1, sA1 + kt);
        cp16(sb + dB0, sB0 + kt);
        cp16(sb + dB1, sB1 + kt);
        cp_commit();
    }

    for (int s = 0; s < 32; s++) {
        if (s < 30) cp_wait1(); else cp_wait0();
        __syncthreads();

        // Issue stage s+2 (overwrites buffer (s+2)%3 = (s-1)%3, safe past barrier).
        if (s + 2 < 32) {
            const uint32_t sb = smu + ((s + 2) % 3) * STG_BYTES;
            const int kt = (s + 2) * 32;
            cp16(sb + dA0, sA0 + kt);
            cp16(sb + dA1, sA1 + kt);
            cp16(sb + dB0, sB0 + kt);
            cp16(sb + dB1, sB1 + kt);
            cp_commit();
        }

        // Compute stage s: 2 k16-steps; 4 A-ldsm + 2 B-ldsm + 16 mma each.
        const uint32_t bufByte = (uint32_t)(s % 3) * STG_BYTES;
        #pragma unroll
        for (int ks = 0; ks < 2; ks++) {
            const uint32_t kByte = bufByte + ks * 32;
            uint32_t af[4][4];
            #pragma unroll
            for (int i = 0; i < 4; i++)
                ldsm4(af[i][0], af[i][1], af[i][2], af[i][3],
                      aLane + kByte + (wm + i * 16) * ROWB);
            #pragma unroll
            for (int j = 0; j < 2; j++) {
                uint32_t m0, m1, m2, m3;
                ldsm4(m0, m1, m2, m3, bLane + kByte + (wn + j * 16) * ROWB);
                uint32_t b0[2] = {m0, m2}, b1[2] = {m1, m3};
                #pragma unroll
                for (int i = 0; i < 4; i++) {
                    mma_f16(acc[i * 4 + 2 * j],     af[i], b0);
                    mma_f16(acc[i * 4 + 2 * j + 1], af[i], b1);
                }
            }
        }
    }

    // Epilogue.
    #pragma unroll
    for (int i = 0; i < 4; i++) {
        const int m0 = bM + wm + i * 16 + g;
        #pragma unroll
        for (int j = 0; j < 4; j++) {
            const int col = bN + wn + j * 8 + 2 * t;
            float2 bb = *(const float2*)(bias + col);
            float v00 = (acc[i * 4 + j][0] + bb.x) * scale;
            float v01 = (acc[i * 4 + j][1] + bb.y) * scale;
            float v10 = (acc[i * 4 + j][2] + bb.x) * scale;
            float v11 = (acc[i * 4 + j][3] + bb.y) * scale;
            if (HALF_OUT) {
                uint32_t* o = (uint32_t*)C;
                o[((size_t)m0 * D_MODEL + col) >> 1]       = f2h2(v00, v01);
                o[((size_t)(m0 + 8) * D_MODEL + col) >> 1] = f2h2(v10, v11);
            } else {
                float* o = (float*)C;
                *(float2*)(o + (size_t)m0 * D_MODEL + col)       = make_float2(v00, v01);
                *(float2*)(o + (size_t)(m0 + 8) * D_MODEL + col) = make_float2(v10, v11);
            }
        }
    }
}

// Fused QKV: gridDim.z selects projection; Q is pre-scaled by 1/8.
__global__ __launch_bounds__(256, 2)
void gemm_qkv(const float* __restrict__ bq, const float* __restrict__ bk,
              const float* __restrict__ bv)
{
    extern __shared__ char smg[];
    const __half* B; const float* bias; __half* C; float scale;
    if (blockIdx.z == 0)      { B = g_Wh;          bias = bq; C = g_Qh; scale = 0.125f; }
    else if (blockIdx.z == 1) { B = g_Wh + DD;     bias = bk; C = g_Kh; scale = 1.0f; }
    else                      { B = g_Wh + 2 * DD; bias = bv; C = g_Vh; scale = 1.0f; }
    gemm_body<true>(g_Xh, B, bias, C, blockIdx.y * 128, blockIdx.x * 128, scale, smg);
}

__global__ __launch_bounds__(256, 2)
void gemm_out(const float* __restrict__ bo, float* __restrict__ out)
{
    extern __shared__ char smg[];
    gemm_body<false>(g_AOh, g_Wh + 3 * DD, bo, out,
                     blockIdx.y * 128, blockIdx.x * 128, 1.0f, smg);
}

// ===========================================================================
// fp16 tensor-core causal flash attention (fp32 softmax), ldmatrix fragments.
// Inputs Q (pre-scaled), K, V are fp16 in gmem -> load loops are pure copies.
// ===========================================================================
#define QT 128
#define KT 64
#define PADW 36
#define ATTN_SMEM_BYTES ((QT + KT + HDIM + QT) * PADW * 4)   // 55296 B

__global__ __launch_bounds__(256, 2)
void attn_mma()
{
    extern __shared__ uint32_t sma[];
    uint32_t* Qs = sma;                  // [128][36w]  Q fp16
    uint32_t* Ks = Qs + QT * PADW;       // [64][36w]   K natural [key][d]
    uint32_t* Vt = Ks + KT * PADW;       // [64][36w]   V transposed [d][key]
    uint32_t* Ps = Vt + HDIM * PADW;     // [128][36w]  P fp16
    __half* Vth = (__half*)Vt;           // half view, pitch 72

    const int tid  = threadIdx.x;
    const int lane = tid & 31;
    const int wid  = tid >> 5;
    const int g    = lane >> 2;
    const int t    = lane & 3;
    const int qt   = (int)(gridDim.x - 1) - (int)blockIdx.x;  // heavy tiles first
    const int h    = blockIdx.y;
    const int n    = blockIdx.z;
    const int qb0  = qt * QT;
    const int row0 = wid * 16;

    const uint32_t laneOfs = (((lane & 15) * PADW + ((lane >> 4) << 2)) << 2);
    const uint32_t qLane = smem_addr_u32(Qs) + laneOfs + ((row0 * PADW) << 2);
    const uint32_t kLane = smem_addr_u32(Ks) + laneOfs;
    const uint32_t vLane = smem_addr_u32(Vt) + laneOfs;
    const uint32_t pLane = smem_addr_u32(Ps) + laneOfs + ((row0 * PADW) << 2);

    const size_t headbase = ((size_t)n * S_LEN) * D_MODEL + h * HDIM;

    // Load Q tile (fp16, already scaled): 128 rows x 8 chunks of 16B.
    {
        const __half* Qg = g_Qh + headbase + (size_t)qb0 * D_MODEL;
        #pragma unroll
        for (int i = 0; i < 4; i++) {
            int idx = tid + i * 256;     // 0..1023
            int r = idx >> 3, c8 = idx & 7;
            uint4 v = *(const uint4*)(Qg + (size_t)r * D_MODEL + c8 * 8);
            *(uint4*)(Qs + r * PADW + c8 * 4) = v;
        }
    }

    float m_i[2] = {-1e30f, -1e30f};
    float l_i[2] = {0.0f, 0.0f};
    float acc[8][4];
    #pragma unroll
    for (int i = 0; i < 8; i++)
        #pragma unroll
        for (int j = 0; j < 4; j++) acc[i][j] = 0.0f;

    const int nkb = (qb0 + QT) / KT;

    for (int kb = 0; kb < nkb; kb++) {
        __syncthreads();
        {
            const __half* Kg = g_Kh + headbase + (size_t)kb * KT * D_MODEL;
            const __half* Vg = g_Vh + headbase + (size_t)kb * KT * D_MODEL;
            #pragma unroll
            for (int i = 0; i < 2; i++) {
                int idx = tid + i * 256;           // 0..511
                int r = idx >> 3, c8 = idx & 7;
                uint4 kv = *(const uint4*)(Kg + (size_t)r * D_MODEL + c8 * 8);
                *(uint4*)(Ks + r * PADW + c8 * 4) = kv;
                // V transpose: 8 scalar half stores, addr = const + lane.
                int rv = idx & 63, cv8 = idx >> 6; // cv8 0..7
                uint4 vv = *(const uint4*)(Vg + (size_t)rv * D_MODEL + cv8 * 8);
                const __half* hv = (const __half*)&vv;
                #pragma unroll
                for (int j = 0; j < 8; j++)
                    Vth[(cv8 * 8 + j) * 72 + rv] = hv[j];
            }
        }
        __syncthreads();

        // ---- S = (Q/8) K^T : 4 k16-steps x 8 n-tiles ----
        float s[8][4];
        #pragma unroll
        for (int i = 0; i < 8; i++)
            #pragma unroll
            for (int j = 0; j < 4; j++) s[i][j] = 0.0f;

        #pragma unroll
        for (int ks = 0; ks < 4; ks++) {
            const uint32_t kByte = ks * 32;
            uint32_t a[4];
            ldsm4(a[0], a[1], a[2], a[3], qLane + kByte);
            #pragma unroll
            for (int j = 0; j < 4; j++) {
                uint32_t m0, m1, m2, m3;
                ldsm4(m0, m1, m2, m3, kLane + kByte + (((j * 16) * PADW) << 2));
                uint32_t b0[2] = {m0, m2}, b1[2] = {m1, m3};
                mma_f16(s[2 * j],     a, b0);
                mma_f16(s[2 * j + 1], a, b1);
            }
        }

        // ---- causal mask ----
        const int r0g = qb0 + row0 + g;
        if ((kb + 1) * KT - 1 > qb0 + row0) {
            #pragma unroll
            for (int nt = 0; nt < 8; nt++) {
                int c = kb * KT + nt * 8 + 2 * t;
                if (c     > r0g)     s[nt][0] = -1e30f;
                if (c + 1 > r0g)     s[nt][1] = -1e30f;
                if (c     > r0g + 8) s[nt][2] = -1e30f;
                if (c + 1 > r0g + 8) s[nt][3] = -1e30f;
            }
        }

        // ---- online softmax (rows g, g+8; quad reduction) ----
        float mx0 = -1e30f, mx1 = -1e30f;
        #pragma unroll
        for (int nt = 0; nt < 8; nt++) {
            mx0 = fmaxf(mx0, fmaxf(s[nt][0], s[nt][1]));
            mx1 = fmaxf(mx1, fmaxf(s[nt][2], s[nt][3]));
        }
        mx0 = fmaxf(mx0, __shfl_xor_sync(0xFFFFFFFFu, mx0, 1));
        mx0 = fmaxf(mx0, __shfl_xor_sync(0xFFFFFFFFu, mx0, 2));
        mx1 = fmaxf(mx1, __shfl_xor_sync(0xFFFFFFFFu, mx1, 1));
        mx1 = fmaxf(mx1, __shfl_xor_sync(0xFFFFFFFFu, mx1, 2));

        const float mn0 = fmaxf(m_i[0], mx0);
        const float mn1 = fmaxf(m_i[1], mx1);
        const float co0 = __expf(m_i[0] - mn0);
        const float co1 = __expf(m_i[1] - mn1);
        m_i[0] = mn0; m_i[1] = mn1;

        float rs0 = 0.0f, rs1 = 0.0f;
        #pragma unroll
        for (int nt = 0; nt < 8; nt++) {
            s[nt][0] = __expf(s[nt][0] - mn0);
            s[nt][1] = __expf(s[nt][1] - mn0);
            s[nt][2] = __expf(s[nt][2] - mn1);
            s[nt][3] = __expf(s[nt][3] - mn1);
            rs0 += s[nt][0] + s[nt][1];
            rs1 += s[nt][2] + s[nt][3];
        }
        rs0 += __shfl_xor_sync(0xFFFFFFFFu, rs0, 1);
        rs0 += __shfl_xor_sync(0xFFFFFFFFu, rs0, 2);
        rs1 += __shfl_xor_sync(0xFFFFFFFFu, rs1, 1);
        rs1 += __shfl_xor_sync(0xFFFFFFFFu, rs1, 2);
        l_i[0] = l_i[0] * co0 + rs0;
        l_i[1] = l_i[1] * co1 + rs1;

        #pragma unroll
        for (int nt = 0; nt < 8; nt++) {
            acc[nt][0] *= co0; acc[nt][1] *= co0;
            acc[nt][2] *= co1; acc[nt][3] *= co1;
        }

        // ---- write P (fp16 half2 words) ----
        {
            uint32_t* p0 = Ps + (row0 + g) * PADW + t;
            uint32_t* p1 = p0 + 8 * PADW;
            #pragma unroll
            for (int nt = 0; nt < 8; nt++) {
                p0[nt * 4] = f2h2(s[nt][0], s[nt][1]);
                p1[nt * 4] = f2h2(s[nt][2], s[nt][3]);
            }
        }
        __syncthreads();

        // ---- acc += P V : 4 k16-steps (keys) x 8 n-tiles (d) ----
        #pragma unroll
        for (int ks = 0; ks < 4; ks++) {
            const uint32_t kByte = ks * 32;
            uint32_t a[4];
            ldsm4(a[0], a[1], a[2], a[3], pLane + kByte);
            #pragma unroll
            for (int j = 0; j < 4; j++) {
                uint32_t m0, m1, m2, m3;
                ldsm4(m0, m1, m2, m3, vLane + kByte + (((j * 16) * PADW) << 2));
                uint32_t b0[2] = {m0, m2}, b1[2] = {m1, m3};
                mma_f16(acc[2 * j],     a, b0);
                mma_f16(acc[2 * j + 1], a, b1);
            }
        }
    }

    // ---- epilogue: normalize, write AO as fp16 ----
    const float inv0 = 1.0f / l_i[0];
    const float inv1 = 1.0f / l_i[1];
    uint32_t* AO = (uint32_t*)g_AOh;
    const size_t w0 = (headbase + (size_t)(qb0 + row0 + g) * D_MODEL) >> 1;
    const size_t w1 = w0 + 4 * D_MODEL;   // +8 rows in half2 words
    #pragma unroll
    for (int nt = 0; nt < 8; nt++) {
        const int c = nt * 8 + 2 * t;     // even
        AO[w0 + (c >> 1)] = f2h2(acc[nt][0] * inv0, acc[nt][1] * inv0);
        AO[w1 + (c >> 1)] = f2h2(acc[nt][2] * inv1, acc[nt][3] * inv1);
    }
}

// ---------------------------------------------------------------------------
// Launch
// ---------------------------------------------------------------------------
extern "C" void kernel_launch(void* const* d_in, const int* in_sizes, int n_in,
                              void* d_out, int out_size)
{
    const float* X  = (const float*)d_in[0];
    const float* Wq = (const float*)d_in[1];
    const float* bq = (const float*)d_in[2];
    const float* Wk = (const float*)d_in[3];
    const float* bk = (const float*)d_in[4];
    const float* Wv = (const float*)d_in[5];
    const float* bv = (const float*)d_in[6];
    const float* Wo = (const float*)d_in[7];
    const float* bo = (const float*)d_in[8];
    float* out = (float*)d_out;

    cudaFuncSetAttribute(gemm_qkv, cudaFuncAttributeMaxDynamicSharedMemorySize,
                         GEMM_SMEM_BYTES);
    cudaFuncSetAttribute(gemm_out, cudaFuncAttributeMaxDynamicSharedMemorySize,
                         GEMM_SMEM_BYTES);
    cudaFuncSetAttribute(attn_mma, cudaFuncAttributeMaxDynamicSharedMemorySize,
                         ATTN_SMEM_BYTES);

    convert_fp16<<<dim3(512, 1, 5), 256>>>(X, Wq, Wk, Wv, Wo);

    dim3 qkv_grid(D_MODEL / 128, NTOK / 128, 3);  // (8, 32, 3)
    dim3 out_grid(D_MODEL / 128, NTOK / 128);     // (8, 32)

    gemm_qkv<<<qkv_grid, 256, GEMM_SMEM_BYTES>>>(bq, bk, bv);

    attn_mma<<<dim3(S_LEN / QT, NH, NBATCH), 256, ATTN_SMEM_BYTES>>>();

    gemm_out<<<out_grid, 256, GEMM_SMEM_BYTES>>>(bo, out);
}

// round 14
// speedup vs baseline: 2.0805x; 1.1476x over previous
#include <cuda_runtime.h>
#include <cuda_fp16.h>
#include <cstdint>

// Problem constants
#define D_MODEL 1024
#define S_LEN   2048
#define NH      16
#define HDIM    64
#define NBATCH  2
#define NTOK    (NBATCH * S_LEN)   // 4096
#define DD      (D_MODEL * D_MODEL)

// Scratch (static __device__ globals — allocation-free per harness rules)
__device__ __half g_Xh [NTOK * D_MODEL];
__device__ __half g_Wh [4 * DD];            // Wq, Wk, Wv, Wo (fp16)
__device__ __half g_Qh [NTOK * D_MODEL];    // pre-scaled by 1/8
__device__ __half g_Kh [NTOK * D_MODEL];
__device__ __half g_Vh [NTOK * D_MODEL];
__device__ __half g_AOh[NTOK * D_MODEL];

// ---------------------------------------------------------------------------
// Helpers (legacy tensor-core path — tcgen05 rejected by sm_100 PTX target).
// ---------------------------------------------------------------------------
__device__ __forceinline__ uint32_t f2h2(float lo, float hi) {
    __half2 h = __floats2half2_rn(lo, hi);
    return *(uint32_t*)&h;
}
__device__ __forceinline__ uint32_t smem_addr_u32(const void* p) {
    return (uint32_t)__cvta_generic_to_shared(p);
}
__device__ __forceinline__ void mma_f16(float* d, const uint32_t* a, const uint32_t* b) {
    asm volatile(
        "mma.sync.aligned.m16n8k16.row.col.f32.f16.f16.f32 "
        "{%0,%1,%2,%3}, {%4,%5,%6,%7}, {%8,%9}, {%0,%1,%2,%3};"
        : "+f"(d[0]), "+f"(d[1]), "+f"(d[2]), "+f"(d[3])
        : "r"(a[0]), "r"(a[1]), "r"(a[2]), "r"(a[3]), "r"(b[0]), "r"(b[1]));
}
__device__ __forceinline__ void ldsm4(uint32_t& r0, uint32_t& r1,
                                      uint32_t& r2, uint32_t& r3, uint32_t addr) {
    asm volatile("ldmatrix.sync.aligned.m8n8.x4.shared.b16 {%0,%1,%2,%3}, [%4];"
                 : "=r"(r0), "=r"(r1), "=r"(r2), "=r"(r3) : "r"(addr));
}
// Transposed variant: loads row-major [k][n] tiles directly as B fragments.
__device__ __forceinline__ void ldsm4t(uint32_t& r0, uint32_t& r1,
                                       uint32_t& r2, uint32_t& r3, uint32_t addr) {
    asm volatile("ldmatrix.sync.aligned.m8n8.x4.trans.shared.b16 {%0,%1,%2,%3}, [%4];"
                 : "=r"(r0), "=r"(r1), "=r"(r2), "=r"(r3) : "r"(addr));
}
__device__ __forceinline__ void cp16(uint32_t dst, const void* src) {
    asm volatile("cp.async.cg.shared.global [%0], [%1], 16;" :: "r"(dst), "l"(src));
}
__device__ __forceinline__ void cp_commit() {
    asm volatile("cp.async.commit_group;" ::: "memory");
}
__device__ __forceinline__ void cp_wait1() {
    asm volatile("cp.async.wait_group 1;" ::: "memory");
}
__device__ __forceinline__ void cp_wait0() {
    asm volatile("cp.async.wait_group 0;" ::: "memory");
}

// ===========================================================================
// fp32 -> fp16 conversion (X + 4 weight matrices).
// ===========================================================================
__global__ void convert_fp16(const float* __restrict__ X,
                             const float* __restrict__ Wq, const float* __restrict__ Wk,
                             const float* __restrict__ Wv, const float* __restrict__ Wo)
{
    const float* src; __half* dst; uint32_t n4;
    switch (blockIdx.z) {
        case 0:  src = X;  dst = g_Xh;          n4 = NTOK * D_MODEL / 4; break;
        case 1:  src = Wq; dst = g_Wh;          n4 = DD / 4; break;
        case 2:  src = Wk; dst = g_Wh + DD;     n4 = DD / 4; break;
        case 3:  src = Wv; dst = g_Wh + 2 * DD; n4 = DD / 4; break;
        default: src = Wo; dst = g_Wh + 3 * DD; n4 = DD / 4; break;
    }
    for (uint32_t i = blockIdx.x * blockDim.x + threadIdx.x; i < n4;
         i += gridDim.x * blockDim.x) {
        float4 v = ((const float4*)src)[i];
        uint2 w = {f2h2(v.x, v.y), f2h2(v.z, v.w)};
        ((uint2*)dst)[i] = w;
    }
}

// ===========================================================================
// fp16 tensor-core GEMM with cp.async 3-stage pipeline (unchanged from R13).
// ===========================================================================
#define ROWB 80
#define STG_BYTES (256 * ROWB)
#define GEMM_SMEM_BYTES (3 * STG_BYTES)         // 61440 B

template <bool HALF_OUT, typename OutT>
__device__ __forceinline__ void gemm_body(
    const __half* __restrict__ A, const __half* __restrict__ B,
    const float* __restrict__ bias, OutT* __restrict__ C,
    int bM, int bN, float scale, void* smv)
{
    const int tid  = threadIdx.x;
    const int lane = tid & 31;
    const int wid  = tid >> 5;
    const int g    = lane >> 2;
    const int t    = lane & 3;
    const int wm   = (wid >> 2) * 64;
    const int wn   = (wid & 3) * 32;

    const uint32_t smu = smem_addr_u32(smv);
    const uint32_t aLane = smu + (lane & 15) * ROWB + ((lane >> 4) << 4);
    const uint32_t bLane = aLane + 128 * ROWB;

    const int ch = tid & 3;
    const int rr = tid >> 2;
    const __half* sA0 = A + (size_t)(bM + rr) * D_MODEL + ch * 8;
    const __half* sA1 = sA0 + (size_t)64 * D_MODEL;
    const __half* sB0 = B + (size_t)(bN + rr) * D_MODEL + ch * 8;
    const __half* sB1 = sB0 + (size_t)64 * D_MODEL;
    const uint32_t dA0 = rr * ROWB + ch * 16;
    const uint32_t dA1 = dA0 + 64 * ROWB;
    const uint32_t dB0 = dA0 + 128 * ROWB;
    const uint32_t dB1 = dB0 + 64 * ROWB;

    float acc[16][4];
    #pragma unroll
    for (int i = 0; i < 16; i++)
        #pragma unroll
        for (int j = 0; j < 4; j++) acc[i][j] = 0.0f;

    #pragma unroll
    for (int s = 0; s < 2; s++) {
        const uint32_t sb = smu + s * STG_BYTES;
        const int kt = s * 32;
        cp16(sb + dA0, sA0 + kt);
        cp16(sb + dA1, sA1 + kt);
        cp16(sb + dB0, sB0 + kt);
        cp16(sb + dB1, sB1 + kt);
        cp_commit();
    }

    for (int s = 0; s < 32; s++) {
        if (s < 30) cp_wait1(); else cp_wait0();
        __syncthreads();

        if (s + 2 < 32) {
            const uint32_t sb = smu + ((s + 2) % 3) * STG_BYTES;
            const int kt = (s + 2) * 32;
            cp16(sb + dA0, sA0 + kt);
            cp16(sb + dA1, sA1 + kt);
            cp16(sb + dB0, sB0 + kt);
            cp16(sb + dB1, sB1 + kt);
            cp_commit();
        }

        const uint32_t bufByte = (uint32_t)(s % 3) * STG_BYTES;
        #pragma unroll
        for (int ks = 0; ks < 2; ks++) {
            const uint32_t kByte = bufByte + ks * 32;
            uint32_t af[4][4];
            #pragma unroll
            for (int i = 0; i < 4; i++)
                ldsm4(af[i][0], af[i][1], af[i][2], af[i][3],
                      aLane + kByte + (wm + i * 16) * ROWB);
            #pragma unroll
            for (int j = 0; j < 2; j++) {
                uint32_t m0, m1, m2, m3;
                ldsm4(m0, m1, m2, m3, bLane + kByte + (wn + j * 16) * ROWB);
                uint32_t b0[2] = {m0, m2}, b1[2] = {m1, m3};
                #pragma unroll
                for (int i = 0; i < 4; i++) {
                    mma_f16(acc[i * 4 + 2 * j],     af[i], b0);
                    mma_f16(acc[i * 4 + 2 * j + 1], af[i], b1);
                }
            }
        }
    }

    #pragma unroll
    for (int i = 0; i < 4; i++) {
        const int m0 = bM + wm + i * 16 + g;
        #pragma unroll
        for (int j = 0; j < 4; j++) {
            const int col = bN + wn + j * 8 + 2 * t;
            float2 bb = *(const float2*)(bias + col);
            float v00 = (acc[i * 4 + j][0] + bb.x) * scale;
            float v01 = (acc[i * 4 + j][1] + bb.y) * scale;
            float v10 = (acc[i * 4 + j][2] + bb.x) * scale;
            float v11 = (acc[i * 4 + j][3] + bb.y) * scale;
            if (HALF_OUT) {
                uint32_t* o = (uint32_t*)C;
                o[((size_t)m0 * D_MODEL + col) >> 1]       = f2h2(v00, v01);
                o[((size_t)(m0 + 8) * D_MODEL + col) >> 1] = f2h2(v10, v11);
            } else {
                float* o = (float*)C;
                *(float2*)(o + (size_t)m0 * D_MODEL + col)       = make_float2(v00, v01);
                *(float2*)(o + (size_t)(m0 + 8) * D_MODEL + col) = make_float2(v10, v11);
            }
        }
    }
}

__global__ __launch_bounds__(256, 2)
void gemm_qkv(const float* __restrict__ bq, const float* __restrict__ bk,
              const float* __restrict__ bv)
{
    extern __shared__ char smg[];
    const __half* B; const float* bias; __half* C; float scale;
    if (blockIdx.z == 0)      { B = g_Wh;          bias = bq; C = g_Qh; scale = 0.125f; }
    else if (blockIdx.z == 1) { B = g_Wh + DD;     bias = bk; C = g_Kh; scale = 1.0f; }
    else                      { B = g_Wh + 2 * DD; bias = bv; C = g_Vh; scale = 1.0f; }
    gemm_body<true>(g_Xh, B, bias, C, blockIdx.y * 128, blockIdx.x * 128, scale, smg);
}

__global__ __launch_bounds__(256, 2)
void gemm_out(const float* __restrict__ bo, float* __restrict__ out)
{
    extern __shared__ char smg[];
    gemm_body<false>(g_AOh, g_Wh + 3 * DD, bo, out,
                     blockIdx.y * 128, blockIdx.x * 128, 1.0f, smg);
}

// ===========================================================================
// fp16 causal flash attention, v2:
//  - P stays in registers (softmax output IS the PV A-fragment)
//  - V consumed from natural [key][d] smem via ldmatrix.x4.trans
//  - K/V tiles double-buffered with cp.async
// Smem: Q [128][36w] + 2 stages x (K [64][36w] + V [64][36w]) = 55296 B.
// ===========================================================================
#define QT 128
#define KT 64
#define PADW 36
#define KV_STG_B (2 * KT * PADW * 4)                  // 18432 B per stage
#define ATTN_SMEM_BYTES (QT * PADW * 4 + 2 * KV_STG_B)  // 55296 B

__global__ __launch_bounds__(256, 2)
void attn_mma()
{
    extern __shared__ uint32_t sma[];
    uint32_t* Qs = sma;                  // [128][36w]
    uint32_t* St = sma + QT * PADW;      // stage0: K,V ; stage1: K,V

    const int tid  = threadIdx.x;
    const int lane = tid & 31;
    const int wid  = tid >> 5;
    const int g    = lane >> 2;
    const int t    = lane & 3;
    const int qt   = (int)(gridDim.x - 1) - (int)blockIdx.x;  // heavy tiles first
    const int h    = blockIdx.y;
    const int n    = blockIdx.z;
    const int qb0  = qt * QT;
    const int row0 = wid * 16;

    const uint32_t laneOfs = (((lane & 15) * PADW + ((lane >> 4) << 2)) << 2);
    const uint32_t qLane  = smem_addr_u32(Qs) + laneOfs + ((row0 * PADW) << 2);
    const uint32_t stBase = smem_addr_u32(St);

    const size_t headbase = ((size_t)n * S_LEN) * D_MODEL + h * HDIM;

    // Q tile (fp16, pre-scaled): plain vector loads.
    {
        const __half* Qg = g_Qh + headbase + (size_t)qb0 * D_MODEL;
        #pragma unroll
        for (int i = 0; i < 4; i++) {
            int idx = tid + i * 256;
            int r = idx >> 3, c8 = idx & 7;
            uint4 v = *(const uint4*)(Qg + (size_t)r * D_MODEL + c8 * 8);
            *(uint4*)(Qs + r * PADW + c8 * 4) = v;
        }
    }

    // cp.async staging: thread covers K rows rK, rK+32 and V rows rK, rK+32
    // (chunk c8 of 8 per 128B row).
    const int c8s = tid & 7;
    const int rKs = tid >> 3;            // 0..31
    const uint32_t dK0 = rKs * 144 + c8s * 16;
    const uint32_t dK1 = dK0 + 32 * 144;
    const uint32_t dV0 = dK0 + KT * 144;
    const uint32_t dV1 = dV0 + 32 * 144;

    float m_i[2] = {-1e30f, -1e30f};
    float l_i[2] = {0.0f, 0.0f};
    float acc[8][4];
    #pragma unroll
    for (int i = 0; i < 8; i++)
        #pragma unroll
        for (int j = 0; j < 4; j++) acc[i][j] = 0.0f;

    const int nkb = (qb0 + QT) / KT;

    // Prologue: stage 0 in flight.
    {
        const __half* Kg = g_Kh + headbase;
        const __half* Vg = g_Vh + headbase;
        const uint32_t sb = stBase;
        cp16(sb + dK0, Kg + (size_t)rKs * D_MODEL + c8s * 8);
        cp16(sb + dK1, Kg + (size_t)(rKs + 32) * D_MODEL + c8s * 8);
        cp16(sb + dV0, Vg + (size_t)rKs * D_MODEL + c8s * 8);
        cp16(sb + dV1, Vg + (size_t)(rKs + 32) * D_MODEL + c8s * 8);
        cp_commit();
    }

    for (int kb = 0; kb < nkb; kb++) {
        __syncthreads();   // all warps done with previous stage's K/V

        if (kb + 1 < nkb) {
            const __half* Kg = g_Kh + headbase + (size_t)(kb + 1) * KT * D_MODEL;
            const __half* Vg = g_Vh + headbase + (size_t)(kb + 1) * KT * D_MODEL;
            const uint32_t sb = stBase + ((kb + 1) & 1) * KV_STG_B;
            cp16(sb + dK0, Kg + (size_t)rKs * D_MODEL + c8s * 8);
            cp16(sb + dK1, Kg + (size_t)(rKs + 32) * D_MODEL + c8s * 8);
            cp16(sb + dV0, Vg + (size_t)rKs * D_MODEL + c8s * 8);
            cp16(sb + dV1, Vg + (size_t)(rKs + 32) * D_MODEL + c8s * 8);
            cp_commit();
            cp_wait1();
        } else {
            cp_wait0();
        }
        __syncthreads();   // stage kb visible to all

        const uint32_t kLane = stBase + (kb & 1) * KV_STG_B + laneOfs;
        const uint32_t vLane = kLane + KT * PADW * 4;

        // ---- S = (Q/8) K^T : 4 k16-steps x 8 n-tiles ----
        float s[8][4];
        #pragma unroll
        for (int i = 0; i < 8; i++)
            #pragma unroll
            for (int j = 0; j < 4; j++) s[i][j] = 0.0f;

        #pragma unroll
        for (int ks = 0; ks < 4; ks++) {
            const uint32_t kByte = ks * 32;
            uint32_t a[4];
            ldsm4(a[0], a[1], a[2], a[3], qLane + kByte);
            #pragma unroll
            for (int j = 0; j < 4; j++) {
                uint32_t m0, m1, m2, m3;
                ldsm4(m0, m1, m2, m3, kLane + kByte + (((j * 16) * PADW) << 2));
                uint32_t b0[2] = {m0, m2}, b1[2] = {m1, m3};
                mma_f16(s[2 * j],     a, b0);
                mma_f16(s[2 * j + 1], a, b1);
            }
        }

        // ---- causal mask ----
        const int r0g = qb0 + row0 + g;
        if ((kb + 1) * KT - 1 > qb0 + row0) {
            #pragma unroll
            for (int nt = 0; nt < 8; nt++) {
                int c = kb * KT + nt * 8 + 2 * t;
                if (c     > r0g)     s[nt][0] = -1e30f;
                if (c + 1 > r0g)     s[nt][1] = -1e30f;
                if (c     > r0g + 8) s[nt][2] = -1e30f;
                if (c + 1 > r0g + 8) s[nt][3] = -1e30f;
            }
        }

        // ---- online softmax (rows g, g+8; quad reduction) ----
        float mx0 = -1e30f, mx1 = -1e30f;
        #pragma unroll
        for (int nt = 0; nt < 8; nt++) {
            mx0 = fmaxf(mx0, fmaxf(s[nt][0], s[nt][1]));
            mx1 = fmaxf(mx1, fmaxf(s[nt][2], s[nt][3]));
        }
        mx0 = fmaxf(mx0, __shfl_xor_sync(0xFFFFFFFFu, mx0, 1));
        mx0 = fmaxf(mx0, __shfl_xor_sync(0xFFFFFFFFu, mx0, 2));
        mx1 = fmaxf(mx1, __shfl_xor_sync(0xFFFFFFFFu, mx1, 1));
        mx1 = fmaxf(mx1, __shfl_xor_sync(0xFFFFFFFFu, mx1, 2));

        const float mn0 = fmaxf(m_i[0], mx0);
        const float mn1 = fmaxf(m_i[1], mx1);
        const float co0 = __expf(m_i[0] - mn0);
        const float co1 = __expf(m_i[1] - mn1);
        m_i[0] = mn0; m_i[1] = mn1;

        float rs0 = 0.0f, rs1 = 0.0f;
        #pragma unroll
        for (int nt = 0; nt < 8; nt++) {
            s[nt][0] = __expf(s[nt][0] - mn0);
            s[nt][1] = __expf(s[nt][1] - mn0);
            s[nt][2] = __expf(s[nt][2] - mn1);
            s[nt][3] = __expf(s[nt][3] - mn1);
            rs0 += s[nt][0] + s[nt][1];
            rs1 += s[nt][2] + s[nt][3];
        }
        rs0 += __shfl_xor_sync(0xFFFFFFFFu, rs0, 1);
        rs0 += __shfl_xor_sync(0xFFFFFFFFu, rs0, 2);
        rs1 += __shfl_xor_sync(0xFFFFFFFFu, rs1, 1);
        rs1 += __shfl_xor_sync(0xFFFFFFFFu, rs1, 2);
        l_i[0] = l_i[0] * co0 + rs0;
        l_i[1] = l_i[1] * co1 + rs1;

        #pragma unroll
        for (int nt = 0; nt < 8; nt++) {
            acc[nt][0] *= co0; acc[nt][1] *= co0;
            acc[nt][2] *= co1; acc[nt][3] *= co1;
        }

        // ---- acc += P V : P packed straight from registers; V via ldsm.trans
        #pragma unroll
        for (int ks = 0; ks < 4; ks++) {
            uint32_t a[4] = {
                f2h2(s[2 * ks][0],     s[2 * ks][1]),
                f2h2(s[2 * ks][2],     s[2 * ks][3]),
                f2h2(s[2 * ks + 1][0], s[2 * ks + 1][1]),
                f2h2(s[2 * ks + 1][2], s[2 * ks + 1][3])
            };
            const uint32_t vRow = vLane + ((ks * 16 * PADW) << 2);
            #pragma unroll
            for (int j = 0; j < 4; j++) {
                uint32_t m0, m1, m2, m3;
                ldsm4t(m0, m1, m2, m3, vRow + j * 32);
                uint32_t b0[2] = {m0, m1}, b1[2] = {m2, m3};
                mma_f16(acc[2 * j],     a, b0);
                mma_f16(acc[2 * j + 1], a, b1);
            }
        }
    }

    // ---- epilogue: normalize, write AO as fp16 ----
    const float inv0 = 1.0f / l_i[0];
    const float inv1 = 1.0f / l_i[1];
    uint32_t* AO = (uint32_t*)g_AOh;
    const size_t w0 = (headbase + (size_t)(qb0 + row0 + g) * D_MODEL) >> 1;
    const size_t w1 = w0 + 4 * D_MODEL;
    #pragma unroll
    for (int nt = 0; nt < 8; nt++) {
        const int c = nt * 8 + 2 * t;
        AO[w0 + (c >> 1)] = f2h2(acc[nt][0] * inv0, acc[nt][1] * inv0);
        AO[w1 + (c >> 1)] = f2h2(acc[nt][2] * inv1, acc[nt][3] * inv1);
    }
}

// ---------------------------------------------------------------------------
// Launch
// ---------------------------------------------------------------------------
extern "C" void kernel_launch(void* const* d_in, const int* in_sizes, int n_in,
                              void* d_out, int out_size)
{
    const float* X  = (const float*)d_in[0];
    const float* Wq = (const float*)d_in[1];
    const float* bq = (const float*)d_in[2];
    const float* Wk = (const float*)d_in[3];
    const float* bk = (const float*)d_in[4];
    const float* Wv = (const float*)d_in[5];
    const float* bv = (const float*)d_in[6];
    const float* Wo = (const float*)d_in[7];
    const float* bo = (const float*)d_in[8];
    float* out = (float*)d_out;

    cudaFuncSetAttribute(gemm_qkv, cudaFuncAttributeMaxDynamicSharedMemorySize,
                         GEMM_SMEM_BYTES);
    cudaFuncSetAttribute(gemm_out, cudaFuncAttributeMaxDynamicSharedMemorySize,
                         GEMM_SMEM_BYTES);
    cudaFuncSetAttribute(attn_mma, cudaFuncAttributeMaxDynamicSharedMemorySize,
                         ATTN_SMEM_BYTES);

    convert_fp16<<<dim3(512, 1, 5), 256>>>(X, Wq, Wk, Wv, Wo);

    dim3 qkv_grid(D_MODEL / 128, NTOK / 128, 3);  // (8, 32, 3)
    dim3 out_grid(D_MODEL / 128, NTOK / 128);     // (8, 32)

    gemm_qkv<<<qkv_grid, 256, GEMM_SMEM_BYTES>>>(bq, bk, bv);

    attn_mma<<<dim3(S_LEN / QT, NH, NBATCH), 256, ATTN_SMEM_BYTES>>>();

    gemm_out<<<out_grid, 256, GEMM_SMEM_BYTES>>>(bo, out);
}